// round 11
// baseline (speedup 1.0000x reference)
#include <cuda_runtime.h>
#include <cuda_bf16.h>
#include <cstdint>

#define NB 16
#define NPOS 4096
#define SCALE 0.17677669529663687f   // 32^-0.5
#define INVN (1.0f / 4096.0f)
#define NCHUNK 8

// ---------------- scratch (device globals; no runtime allocation) ----------------
__device__ __nv_bfloat16 g_qkvh[(size_t)NB * 384 * NPOS]; // q(raw)/k(FiLM)/v(FiLM,/n) bf16
__device__ __nv_bfloat16 g_xh[(size_t)NB * 256 * NPOS];   // X bf16, same [b][k][n] layout
__device__ float g_film[NB * 512];
__device__ float g_Sp[NCHUNK * NB * 4 * 32 * 32];
__device__ float g_Zp[NCHUNK * NB * 128];
__device__ __nv_bfloat16 g_Mb[NB * 256 * 128];            // M_b bf16, k contiguous
__device__ __nv_bfloat16 g_wt[384 * 256];                 // W_qkv bf16, k contiguous

// ================= helpers =================
__device__ __forceinline__ uint32_t smem_u32(const void* p) {
    uint32_t a;
    asm("{ .reg .u64 t; cvta.to.shared.u64 t, %1; cvt.u32.u64 %0, t; }" : "=r"(a) : "l"(p));
    return a;
}
__device__ __forceinline__ void cpa16(uint32_t dst, const void* src) {
    asm volatile("cp.async.cg.shared.global [%0], [%1], 16;"
                 :: "r"(dst), "l"(__cvta_generic_to_global(src)));
}
#define CPA_COMMIT() asm volatile("cp.async.commit_group;" ::: "memory")
#define CPA_WAIT0()  asm volatile("cp.async.wait_group 0;" ::: "memory")
#define CPA_WAIT1()  asm volatile("cp.async.wait_group 1;" ::: "memory")
#define CPA_WAIT2()  asm volatile("cp.async.wait_group 2;" ::: "memory")

__device__ __forceinline__ void mma_bf16(float c[4], const uint32_t a[4], const uint32_t b[2]) {
    asm volatile(
        "mma.sync.aligned.m16n8k16.row.col.f32.bf16.bf16.f32 "
        "{%0,%1,%2,%3}, {%4,%5,%6,%7}, {%8,%9}, {%0,%1,%2,%3};\n"
        : "+f"(c[0]), "+f"(c[1]), "+f"(c[2]), "+f"(c[3])
        : "r"(a[0]), "r"(a[1]), "r"(a[2]), "r"(a[3]), "r"(b[0]), "r"(b[1]));
}
__device__ __forceinline__ void ldm_x4(uint32_t r[4], uint32_t addr) {
    asm volatile("ldmatrix.sync.aligned.m8n8.x4.shared.b16 {%0,%1,%2,%3}, [%4];"
                 : "=r"(r[0]), "=r"(r[1]), "=r"(r[2]), "=r"(r[3]) : "r"(addr));
}
__device__ __forceinline__ void ldm_x2(uint32_t r[2], uint32_t addr) {
    asm volatile("ldmatrix.sync.aligned.m8n8.x2.shared.b16 {%0,%1}, [%2];"
                 : "=r"(r[0]), "=r"(r[1]) : "r"(addr));
}
__device__ __forceinline__ void ldm_x4t(uint32_t& r0, uint32_t& r1, uint32_t& r2, uint32_t& r3,
                                        uint32_t addr) {
    asm volatile("ldmatrix.sync.aligned.m8n8.x4.trans.shared.b16 {%0,%1,%2,%3}, [%4];"
                 : "=r"(r0), "=r"(r1), "=r"(r2), "=r"(r3) : "r"(addr));
}
__device__ __forceinline__ void filmAB(int m, const float* __restrict__ fb,
                                       float& alpha, float& beta) {
    alpha = 1.0f; beta = 0.0f;
    if (m >= 256) {
        int c = m - 256;
        alpha = (1.0f + fb[256 + c]) * INVN;
        beta = fb[384 + c] * INVN;
    } else if (m >= 128) {
        int c = m - 128;
        alpha = 1.0f + fb[c];
        beta = fb[128 + c];
    }
}

// ================= prep: fused xconv + wconv + film =================
// grid: [0,16384) xconv, [16384,16480) wconv, [16480,16496) film. 256 threads.
__global__ void prep_kernel(const float* __restrict__ X,
                            const float* __restrict__ W,
                            const float* __restrict__ cond,
                            const float* __restrict__ Wc,
                            const float* __restrict__ bc) {
    int blk = blockIdx.x, t = threadIdx.x;
    if (blk < 16384) {
        size_t i = ((size_t)blk * 256 + t) * 4;
        float4 v = *(const float4*)(X + i);
        __nv_bfloat162 p0 = __floats2bfloat162_rn(v.x, v.y);
        __nv_bfloat162 p1 = __floats2bfloat162_rn(v.z, v.w);
        uint2 u;
        u.x = *(uint32_t*)&p0;
        u.y = *(uint32_t*)&p1;
        *(uint2*)(g_xh + i) = u;
    } else if (blk < 16480) {
        size_t i = ((size_t)(blk - 16384) * 256 + t) * 4;
        float4 v = *(const float4*)(W + i);
        __nv_bfloat162 p0 = __floats2bfloat162_rn(v.x, v.y);
        __nv_bfloat162 p1 = __floats2bfloat162_rn(v.z, v.w);
        uint2 u;
        u.x = *(uint32_t*)&p0;
        u.y = *(uint32_t*)&p1;
        *(uint2*)(g_wt + i) = u;
    } else {
        int b = blk - 16480;
        __shared__ float sc[256];
        float xv = cond[b * 256 + t];
        sc[t] = xv / (1.0f + __expf(-xv));
        __syncthreads();
#pragma unroll
        for (int rr = 0; rr < 2; rr++) {
            int r = t + rr * 256;
            const float* wr = Wc + r * 256;
            float acc = bc[r];
#pragma unroll 8
            for (int j = 0; j < 256; j++) acc += wr[j] * sc[j];
            g_film[b * 512 + r] = acc;
        }
    }
}

// ================= qkv GEMM: 4-stage cp.async, all-bf16 operands =================
#define QST 18944   // stage stride bytes = 10240 (A) + 8704 (B)
#define QKV_SMEM (4 * QST)

__global__ void __launch_bounds__(256, 2) qkv_mma(void) {
    extern __shared__ uint8_t qs[];
    uint32_t sb = smem_u32(qs);

    int b = blockIdx.z, grp = blockIdx.x;
    int m0 = grp * 128, n0 = blockIdx.y * 128;
    int t = threadIdx.x, lane = t & 31, w = t >> 5;
    int wr = w >> 2, wc = w & 3;
    int lq = lane >> 2, lr = lane & 3;

    float acc[4][4][4];
#pragma unroll
    for (int mt = 0; mt < 4; mt++)
#pragma unroll
        for (int nt = 0; nt < 4; nt++)
#pragma unroll
            for (int r = 0; r < 4; r++) acc[mt][nt][r] = 0.0f;

    int cA0 = 2 * t, cA1 = 2 * t + 1;
    int aR0 = cA0 >> 2, aS0 = cA0 & 3;
    int aR1 = cA1 >> 2, aS1 = cA1 & 3;
    int bR0 = cA0 >> 4, bS0 = cA0 & 15;
    int bR1 = cA1 >> 4, bS1 = cA1 & 15;
    const __nv_bfloat16* gA0 = g_wt + (size_t)(m0 + aR0) * 256 + aS0 * 8;
    const __nv_bfloat16* gA1 = g_wt + (size_t)(m0 + aR1) * 256 + aS1 * 8;
    const __nv_bfloat16* gB0 = g_xh + ((size_t)b * 256 + bR0) * NPOS + n0 + bS0 * 8;
    const __nv_bfloat16* gB1 = g_xh + ((size_t)b * 256 + bR1) * NPOS + n0 + bS1 * 8;
    uint32_t dA0 = aR0 * 80 + aS0 * 16, dA1 = aR1 * 80 + aS1 * 16;
    uint32_t dB0 = 10240 + bR0 * 272 + bS0 * 16, dB1 = 10240 + bR1 * 272 + bS1 * 16;

#define LOADSTAGE(s, k0)                                                   \
    {                                                                      \
        uint32_t stb = sb + (s) * QST;                                     \
        cpa16(stb + dA0, gA0 + (k0));                                      \
        cpa16(stb + dA1, gA1 + (k0));                                      \
        cpa16(stb + dB0, gB0 + (size_t)(k0) * NPOS);                       \
        cpa16(stb + dB1, gB1 + (size_t)(k0) * NPOS);                       \
        CPA_COMMIT();                                                      \
    }

    uint32_t aOff = (uint32_t)(wr * 64 + (lane & 15)) * 80 + ((lane >> 4) << 3) * 2;
    uint32_t bOff = 10240 + (uint32_t)(((lane >> 3) & 1) * 8 + (lane & 7)) * 272 +
                    (uint32_t)(wc * 32 + ((lane >> 4) << 3)) * 2;

    LOADSTAGE(0, 0);
    LOADSTAGE(1, 32);
    LOADSTAGE(2, 64);

    for (int kk = 0; kk < 8; kk++) {
        int st = kk & 3;
        if (kk <= 5) { CPA_WAIT2(); } else if (kk == 6) { CPA_WAIT1(); } else { CPA_WAIT0(); }
        __syncthreads();
        if (kk + 3 < 8) LOADSTAGE((kk + 3) & 3, (kk + 3) * 32);
        uint32_t stb = sb + st * QST;
#pragma unroll
        for (int kh = 0; kh < 2; kh++) {
            uint32_t af[4][4];
#pragma unroll
            for (int mt = 0; mt < 4; mt++)
                ldm_x4(af[mt], stb + aOff + mt * 1280 + kh * 32);
            uint32_t bfr[4][2];
#pragma unroll
            for (int pr = 0; pr < 2; pr++) {
                uint32_t r0, r1, r2, r3;
                ldm_x4t(r0, r1, r2, r3, stb + bOff + kh * 4352 + pr * 32);
                bfr[2 * pr][0] = r0; bfr[2 * pr][1] = r1;
                bfr[2 * pr + 1][0] = r2; bfr[2 * pr + 1][1] = r3;
            }
#pragma unroll
            for (int mt = 0; mt < 4; mt++)
#pragma unroll
                for (int nt = 0; nt < 4; nt++) mma_bf16(acc[mt][nt], af[mt], bfr[nt]);
        }
    }

    const float* fb = g_film + b * 512;
    __nv_bfloat16* C = g_qkvh + (size_t)b * 384 * NPOS;
#pragma unroll
    for (int mt = 0; mt < 4; mt++) {
        int mA = m0 + wr * 64 + mt * 16 + lq;
        int mB = mA + 8;
        float aA, bA, aB, bB;
        filmAB(mA, fb, aA, bA);
        filmAB(mB, fb, aB, bB);
#pragma unroll
        for (int nt = 0; nt < 4; nt++) {
            int cc = n0 + wc * 32 + nt * 8 + 2 * lr;
            __nv_bfloat162 o0 = __floats2bfloat162_rn(fmaf(aA, acc[mt][nt][0], bA),
                                                      fmaf(aA, acc[mt][nt][1], bA));
            __nv_bfloat162 o1 = __floats2bfloat162_rn(fmaf(aB, acc[mt][nt][2], bB),
                                                      fmaf(aB, acc[mt][nt][3], bB));
            *(__nv_bfloat162*)&C[(size_t)mA * NPOS + cc] = o0;
            *(__nv_bfloat162*)&C[(size_t)mB * NPOS + cc] = o1;
        }
    }
}

// ================= ctx via mma: no-max exp, dual accumulator chains =================
#define KSE 520
__global__ void __launch_bounds__(256) ctx_mma() {
    extern __shared__ __nv_bfloat16 cs[];
    __nv_bfloat16* Ks = cs;
    __nv_bfloat16* Vs = cs + 32 * KSE;

    int b = blockIdx.z, h = blockIdx.y, chunk = blockIdx.x;
    int t = threadIdx.x;

    const __nv_bfloat16* Kg = g_qkvh + ((size_t)b * 384 + 128 + h * 32) * NPOS + chunk * 512;
    const __nv_bfloat16* Vg = Kg + (size_t)128 * NPOS;
    for (int i = t; i < 2048; i += 256) {
        int row = i >> 6, col = i & 63;
        *(uint4*)&Ks[row * KSE + col * 8] = *(const uint4*)(Kg + (size_t)row * NPOS + col * 8);
        *(uint4*)&Vs[row * KSE + col * 8] = *(const uint4*)(Vg + (size_t)row * NPOS + col * 8);
    }
    __syncthreads();

    // E = exp(k) in place (bf16), z = sum E
    int c = t >> 3, sub = t & 7;
    __nv_bfloat16* Kr = Ks + c * KSE + sub * 64;
    float z = 0.f;
#pragma unroll
    for (int j4 = 0; j4 < 8; j4++) {
        uint4 kv = *(uint4*)&Kr[j4 * 8];
        __nv_bfloat162* kp = (__nv_bfloat162*)&kv;
        uint4 ev;
        __nv_bfloat162* ep = (__nv_bfloat162*)&ev;
#pragma unroll
        for (int p = 0; p < 4; p++) {
            float2 f = __bfloat1622float2(kp[p]);
            __nv_bfloat162 e2 = __floats2bfloat162_rn(__expf(f.x), __expf(f.y));
            ep[p] = e2;
            float2 ef = __bfloat1622float2(e2);
            z += ef.x + ef.y;
        }
        *(uint4*)&Kr[j4 * 8] = ev;
    }
#pragma unroll
    for (int o = 1; o < 8; o <<= 1) z += __shfl_xor_sync(0xffffffffu, z, o);
    if (sub == 0) g_Zp[((size_t)chunk * NB + b) * 128 + h * 32 + c] = z;
    __syncthreads();

    // S(32x32) = E @ V^T, dual chains (even/odd k-step) for ILP
    int w = t >> 5, lane = t & 31;
    int mrow = (w & 1) * 16, ncol = (w >> 1) * 8;
    uint32_t Eb = smem_u32(Ks), Vb = smem_u32(Vs);
    uint32_t aAddr = Eb + ((mrow + (lane & 15)) * KSE + ((lane >> 4) << 3)) * 2;
    uint32_t bAddr = Vb + ((ncol + (lane & 7)) * KSE + (((lane >> 3) & 3) << 3)) * 2;
    float acc0[4] = {0.f, 0.f, 0.f, 0.f};
    float acc1[4] = {0.f, 0.f, 0.f, 0.f};
#pragma unroll
    for (int ks = 0; ks < 32; ks += 2) {
        uint32_t a0[4], b0[2], a1[4], b1[2];
        ldm_x4(a0, aAddr + ks * 32);
        ldm_x2(b0, bAddr + ks * 32);
        ldm_x4(a1, aAddr + ks * 32 + 32);
        ldm_x2(b1, bAddr + ks * 32 + 32);
        mma_bf16(acc0, a0, b0);
        mma_bf16(acc1, a1, b1);
    }
    int lq = lane >> 2, lr = lane & 3;
    float* Sp = g_Sp + (((size_t)chunk * NB + b) * 4 + h) * 1024;
    Sp[(mrow + lq) * 32 + ncol + 2 * lr] = acc0[0] + acc1[0];
    Sp[(mrow + lq) * 32 + ncol + 2 * lr + 1] = acc0[1] + acc1[1];
    Sp[(mrow + lq + 8) * 32 + ncol + 2 * lr] = acc0[2] + acc1[2];
    Sp[(mrow + lq + 8) * 32 + ncol + 2 * lr + 1] = acc0[3] + acc1[3];
}

// ---------------- build M_b: 64 CTAs (4 row-segments x batch) ----------------
__global__ void buildM_kernel(const float* __restrict__ Wout) {
    int seg = blockIdx.x, b = blockIdx.y, t = threadIdx.x;
    __shared__ float ctxs[4096];
    __shared__ float zsm[128];
    if (t < 128) {
        float zz = 0.f;
#pragma unroll
        for (int ch = 0; ch < NCHUNK; ch++) zz += g_Zp[((size_t)ch * NB + b) * 128 + t];
        zsm[t] = zz;
    }
    __syncthreads();
    for (int i = t; i < 4096; i += 256) {
        int h = i >> 10, c = (i >> 5) & 31;
        int chan = h * 32 + c;
        float s = 0.f;
#pragma unroll
        for (int ch = 0; ch < NCHUNK; ch++)
            s += g_Sp[((size_t)ch * NB + b) * 4096 + i];
        ctxs[i] = s / zsm[chan];
    }
    __syncthreads();
    int row = seg * 64 + (t & 63);
    int g = t >> 6;
    const float* wr = Wout + row * 128 + g * 32;
    float wv[32];
#pragma unroll
    for (int e = 0; e < 32; e++) wv[e] = wr[e];
    __nv_bfloat16* Mr = g_Mb + (size_t)b * 32768 + row * 128 + g * 32;
    for (int c2 = 0; c2 < 32; c2++) {
        float s = 0.f;
#pragma unroll
        for (int e = 0; e < 32; e++) s += wv[e] * ctxs[g * 1024 + c2 * 32 + e];
        Mr[c2] = __float2bfloat16(s);
    }
}

// ---------------- final v4: 256 thr / 64 cols, KW2=68 -> 2 CTAs/SM ----------------
#define KW2 68
#define FO_M   0               // 256*68 = 17408 words
#define FO_Q   17408           // 64*68 = 4352 words
#define FO_B   21760           // 256
#define FO_G   22016           // 256
#define FO_WS  22272           // 8*32 = 256
#define FO_WQ  22528           // 256
#define FO_CS  22784           // 64
#define FO_CQ  22848           // 64
#define F_TOT  22912           // words = 91648 bytes

__global__ void __launch_bounds__(256, 2) final_mma(const float* __restrict__ bout,
                                                    const float* __restrict__ gam,
                                                    float* __restrict__ out) {
    extern __shared__ uint32_t fsm[];
    uint32_t* Msm = fsm + FO_M;
    uint32_t* Qsm = fsm + FO_Q;
    float* bsm = (float*)(fsm + FO_B);
    float* gsm = (float*)(fsm + FO_G);
    float* wsum = (float*)(fsm + FO_WS);
    float* wsq = (float*)(fsm + FO_WQ);
    float* csum = (float*)(fsm + FO_CS);
    float* csq = (float*)(fsm + FO_CQ);

    int b = blockIdx.y, n0 = blockIdx.x * 64, t = threadIdx.x;
    int lane = t & 31, w = t >> 5;
    int wm = w >> 1, wn = w & 1;
    int lq = lane >> 2, lr = lane & 3;

    // M tile via one cp.async group (overlaps with register q softmax below)
    const __nv_bfloat16* Mg = g_Mb + (size_t)b * 32768;
#pragma unroll
    for (int j = 0; j < 16; j++) {
        int c = t + 256 * j;           // 4096 chunks of 16B
        int row = c >> 4, seg = c & 15;
        cpa16(smem_u32(&Msm[row * KW2 + seg * 4]), Mg + row * 128 + seg * 8);
    }
    CPA_COMMIT();

    bsm[t] = bout[t];
    gsm[t] = gam[t];

    // q softmax from global into Qsm fragments: thread = (head h, col)
    {
        int h = t >> 6, col = t & 63;
        const __nv_bfloat16* Qc = g_qkvh + (size_t)b * 384 * NPOS + (size_t)(h * 32) * NPOS + n0 + col;
        float v[32];
        float ssum = 0.f;
#pragma unroll
        for (int i = 0; i < 32; i++) {
            v[i] = __expf(__bfloat162float(Qc[(size_t)i * NPOS]));
            ssum += v[i];
        }
        float inv = SCALE / ssum;
#pragma unroll
        for (int i2 = 0; i2 < 16; i2++) {
            __nv_bfloat162 p = __floats2bfloat162_rn(v[2 * i2] * inv, v[2 * i2 + 1] * inv);
            Qsm[col * KW2 + h * 16 + i2] = *(uint32_t*)&p;
        }
    }
    CPA_WAIT0();
    __syncthreads();

    float acc[4][4][4];
#pragma unroll
    for (int mt = 0; mt < 4; mt++)
#pragma unroll
        for (int nt = 0; nt < 4; nt++)
#pragma unroll
            for (int r = 0; r < 4; r++) acc[mt][nt][r] = 0.0f;

#pragma unroll
    for (int ks = 0; ks < 8; ks++) {
        int ksw = ks * 8;
        uint32_t af[4][4], bfr[4][2];
#pragma unroll
        for (int mt = 0; mt < 4; mt++) {
            int r0 = wm * 64 + mt * 16 + lq;
            af[mt][0] = Msm[r0 * KW2 + ksw + lr];
            af[mt][1] = Msm[(r0 + 8) * KW2 + ksw + lr];
            af[mt][2] = Msm[r0 * KW2 + ksw + lr + 4];
            af[mt][3] = Msm[(r0 + 8) * KW2 + ksw + lr + 4];
        }
#pragma unroll
        for (int nt = 0; nt < 4; nt++) {
            int n = wn * 32 + nt * 8 + lq;
            bfr[nt][0] = Qsm[n * KW2 + ksw + lr];
            bfr[nt][1] = Qsm[n * KW2 + ksw + lr + 4];
        }
#pragma unroll
        for (int mt = 0; mt < 4; mt++)
#pragma unroll
            for (int nt = 0; nt < 4; nt++) mma_bf16(acc[mt][nt], af[mt], bfr[nt]);
    }

    // + bias, per-column partial stats
    float ps[4][2], pq[4][2];
#pragma unroll
    for (int nt = 0; nt < 4; nt++)
#pragma unroll
        for (int j = 0; j < 2; j++) { ps[nt][j] = 0.f; pq[nt][j] = 0.f; }
#pragma unroll
    for (int mt = 0; mt < 4; mt++) {
        float b0v = bsm[wm * 64 + mt * 16 + lq];
        float b1v = bsm[wm * 64 + mt * 16 + lq + 8];
#pragma unroll
        for (int nt = 0; nt < 4; nt++) {
            acc[mt][nt][0] += b0v; acc[mt][nt][1] += b0v;
            acc[mt][nt][2] += b1v; acc[mt][nt][3] += b1v;
#pragma unroll
            for (int j = 0; j < 2; j++) {
                float v0 = acc[mt][nt][j], v1 = acc[mt][nt][2 + j];
                ps[nt][j] += v0 + v1;
                pq[nt][j] += v0 * v0 + v1 * v1;
            }
        }
    }
#pragma unroll
    for (int nt = 0; nt < 4; nt++)
#pragma unroll
        for (int j = 0; j < 2; j++) {
#pragma unroll
            for (int o = 4; o <= 16; o <<= 1) {
                ps[nt][j] += __shfl_xor_sync(0xffffffffu, ps[nt][j], o);
                pq[nt][j] += __shfl_xor_sync(0xffffffffu, pq[nt][j], o);
            }
        }
    if (lq == 0) {
#pragma unroll
        for (int nt = 0; nt < 4; nt++)
#pragma unroll
            for (int j = 0; j < 2; j++) {
                wsum[w * 32 + nt * 8 + 2 * lr + j] = ps[nt][j];
                wsq[w * 32 + nt * 8 + 2 * lr + j] = pq[nt][j];
            }
    }
    __syncthreads();
    if (t < 64) {
        int wnc = t >> 5, cl = t & 31;
        float sx = 0.f, sq2 = 0.f;
#pragma unroll
        for (int k = 0; k < 4; k++) {
            sx += wsum[(k * 2 + wnc) * 32 + cl];
            sq2 += wsq[(k * 2 + wnc) * 32 + cl];
        }
        csum[t] = sx;
        csq[t] = sq2;
    }
    __syncthreads();

    float mean[4][2], rs[4][2];
#pragma unroll
    for (int nt = 0; nt < 4; nt++)
#pragma unroll
        for (int j = 0; j < 2; j++) {
            int cg = wn * 32 + nt * 8 + 2 * lr + j;
            float mu = csum[cg] * (1.0f / 256.0f);
            float var = csq[cg] * (1.0f / 256.0f) - mu * mu;
            mean[nt][j] = mu;
            rs[nt][j] = rsqrtf(var + 1e-5f);
        }
#pragma unroll
    for (int mt = 0; mt < 4; mt++) {
        int r0 = wm * 64 + mt * 16 + lq;
        float g0 = gsm[r0], g1 = gsm[r0 + 8];
#pragma unroll
        for (int nt = 0; nt < 4; nt++) {
            int cc = n0 + wn * 32 + nt * 8 + 2 * lr;
            float2 o0, o1;
            o0.x = (acc[mt][nt][0] - mean[nt][0]) * rs[nt][0] * g0;
            o0.y = (acc[mt][nt][1] - mean[nt][1]) * rs[nt][1] * g0;
            o1.x = (acc[mt][nt][2] - mean[nt][0]) * rs[nt][0] * g1;
            o1.y = (acc[mt][nt][3] - mean[nt][1]) * rs[nt][1] * g1;
            *(float2*)&out[((size_t)(b * 256 + r0)) * NPOS + cc] = o0;
            *(float2*)&out[((size_t)(b * 256 + r0 + 8)) * NPOS + cc] = o1;
        }
    }
}

// ---------------- launch ----------------
extern "C" void kernel_launch(void* const* d_in, const int* in_sizes, int n_in,
                              void* d_out, int out_size) {
    (void)in_sizes; (void)n_in; (void)out_size;
    const float* x = (const float*)d_in[0];
    const float* cond = (const float*)d_in[1];
    const float* W_qkv = (const float*)d_in[2];
    const float* W_cond = (const float*)d_in[3];
    const float* b_cond = (const float*)d_in[4];
    const float* W_out = (const float*)d_in[5];
    const float* b_out = (const float*)d_in[6];
    const float* g = (const float*)d_in[7];
    float* out = (float*)d_out;

    prep_kernel<<<16496, 256>>>(x, W_qkv, cond, W_cond, b_cond);

    cudaFuncSetAttribute(qkv_mma, cudaFuncAttributeMaxDynamicSharedMemorySize, QKV_SMEM);
    qkv_mma<<<dim3(3, 32, NB), 256, QKV_SMEM>>>();

    int ctx_smem = 2 * 32 * KSE * (int)sizeof(__nv_bfloat16);
    cudaFuncSetAttribute(ctx_mma, cudaFuncAttributeMaxDynamicSharedMemorySize, ctx_smem);
    ctx_mma<<<dim3(NCHUNK, 4, NB), 256, ctx_smem>>>();

    buildM_kernel<<<dim3(4, NB), 256>>>(W_out);

    int smbytes = F_TOT * (int)sizeof(uint32_t);
    cudaFuncSetAttribute(final_mma, cudaFuncAttributeMaxDynamicSharedMemorySize, smbytes);
    final_mma<<<dim3(64, NB), 256, smbytes>>>(b_out, g, out);
}

// round 12
// speedup vs baseline: 1.2216x; 1.2216x over previous
#include <cuda_runtime.h>
#include <cuda_bf16.h>
#include <cstdint>

#define NB 16
#define NPOS 4096
#define SCALE 0.17677669529663687f   // 32^-0.5
#define INVN (1.0f / 4096.0f)
#define NCHUNK 8

// ---------------- scratch (device globals; no runtime allocation) ----------------
__device__ __nv_bfloat16 g_qkvh[(size_t)NB * 384 * NPOS]; // q(raw)/k(FiLM)/v(FiLM,/n) bf16
__device__ __nv_bfloat16 g_xh[(size_t)NB * 256 * NPOS];   // X bf16, same [b][k][n] layout
__device__ float g_film[NB * 512];
__device__ float g_Sp[NCHUNK * NB * 4 * 32 * 32];
__device__ float g_Zp[NCHUNK * NB * 128];
__device__ float g_ctx[NB * 4096];                        // normalized context per batch
__device__ __nv_bfloat16 g_Mb[NB * 256 * 128];            // M_b bf16, k contiguous
__device__ __nv_bfloat16 g_wt[384 * 256];                 // W_qkv bf16, k contiguous

// ---------------- FiLM ----------------
__global__ void film_kernel(const float* __restrict__ cond,
                            const float* __restrict__ Wc,
                            const float* __restrict__ bc) {
    int b = blockIdx.x, t = threadIdx.x;
    __shared__ float sc[256];
    if (t < 256) {
        float xv = cond[b * 256 + t];
        sc[t] = xv / (1.0f + __expf(-xv));
    }
    __syncthreads();
    const float* wr = Wc + t * 256;
    float acc = bc[t];
#pragma unroll 8
    for (int j = 0; j < 256; j++) acc += wr[j] * sc[j];
    g_film[b * 512 + t] = acc;
}

__global__ void wconv_kernel(const float* __restrict__ W) {
    int i = blockIdx.x * 1024 + threadIdx.x;
    if (i < 384 * 256) g_wt[i] = __float2bfloat16(W[i]);
}

// X fp32 -> bf16, identity layout, vectorized
__global__ void xconv_kernel(const float* __restrict__ X) {
    size_t i = ((size_t)blockIdx.x * 256 + threadIdx.x) * 4;
    float4 v = *(const float4*)(X + i);
    __nv_bfloat162 p0 = __floats2bfloat162_rn(v.x, v.y);
    __nv_bfloat162 p1 = __floats2bfloat162_rn(v.z, v.w);
    uint2 u;
    u.x = *(uint32_t*)&p0;
    u.y = *(uint32_t*)&p1;
    *(uint2*)(g_xh + i) = u;
}

// ================= helpers =================
__device__ __forceinline__ uint32_t smem_u32(const void* p) {
    uint32_t a;
    asm("{ .reg .u64 t; cvta.to.shared.u64 t, %1; cvt.u32.u64 %0, t; }" : "=r"(a) : "l"(p));
    return a;
}
__device__ __forceinline__ void cpa16(uint32_t dst, const void* src) {
    asm volatile("cp.async.cg.shared.global [%0], [%1], 16;"
                 :: "r"(dst), "l"(__cvta_generic_to_global(src)));
}
#define CPA_COMMIT() asm volatile("cp.async.commit_group;" ::: "memory")
#define CPA_WAIT0()  asm volatile("cp.async.wait_group 0;" ::: "memory")
#define CPA_WAIT1()  asm volatile("cp.async.wait_group 1;" ::: "memory")
#define CPA_WAIT2()  asm volatile("cp.async.wait_group 2;" ::: "memory")

__device__ __forceinline__ void mma_bf16(float c[4], const uint32_t a[4], const uint32_t b[2]) {
    asm volatile(
        "mma.sync.aligned.m16n8k16.row.col.f32.bf16.bf16.f32 "
        "{%0,%1,%2,%3}, {%4,%5,%6,%7}, {%8,%9}, {%0,%1,%2,%3};\n"
        : "+f"(c[0]), "+f"(c[1]), "+f"(c[2]), "+f"(c[3])
        : "r"(a[0]), "r"(a[1]), "r"(a[2]), "r"(a[3]), "r"(b[0]), "r"(b[1]));
}
__device__ __forceinline__ void ldm_x4(uint32_t r[4], uint32_t addr) {
    asm volatile("ldmatrix.sync.aligned.m8n8.x4.shared.b16 {%0,%1,%2,%3}, [%4];"
                 : "=r"(r[0]), "=r"(r[1]), "=r"(r[2]), "=r"(r[3]) : "r"(addr));
}
__device__ __forceinline__ void ldm_x2(uint32_t r[2], uint32_t addr) {
    asm volatile("ldmatrix.sync.aligned.m8n8.x2.shared.b16 {%0,%1}, [%2];"
                 : "=r"(r[0]), "=r"(r[1]) : "r"(addr));
}
__device__ __forceinline__ void ldm_x4t(uint32_t& r0, uint32_t& r1, uint32_t& r2, uint32_t& r3,
                                        uint32_t addr) {
    asm volatile("ldmatrix.sync.aligned.m8n8.x4.trans.shared.b16 {%0,%1,%2,%3}, [%4];"
                 : "=r"(r0), "=r"(r1), "=r"(r2), "=r"(r3) : "r"(addr));
}
__device__ __forceinline__ void filmAB(int m, const float* __restrict__ fb,
                                       float& alpha, float& beta) {
    alpha = 1.0f; beta = 0.0f;
    if (m >= 256) {
        int c = m - 256;
        alpha = (1.0f + fb[256 + c]) * INVN;
        beta = fb[384 + c] * INVN;
    } else if (m >= 128) {
        int c = m - 128;
        alpha = 1.0f + fb[c];
        beta = fb[128 + c];
    }
}

// ================= qkv GEMM: 4-stage cp.async, all-bf16 operands =================
#define QST 18944   // stage stride bytes = 10240 (A) + 8704 (B)
#define QKV_SMEM (4 * QST)

__global__ void __launch_bounds__(256, 2) qkv_mma(void) {
    extern __shared__ uint8_t qs[];
    uint32_t sb = smem_u32(qs);

    int b = blockIdx.z, grp = blockIdx.x;
    int m0 = grp * 128, n0 = blockIdx.y * 128;
    int t = threadIdx.x, lane = t & 31, w = t >> 5;
    int wr = w >> 2, wc = w & 3;
    int lq = lane >> 2, lr = lane & 3;

    float acc[4][4][4];
#pragma unroll
    for (int mt = 0; mt < 4; mt++)
#pragma unroll
        for (int nt = 0; nt < 4; nt++)
#pragma unroll
            for (int r = 0; r < 4; r++) acc[mt][nt][r] = 0.0f;

    int cA0 = 2 * t, cA1 = 2 * t + 1;
    int aR0 = cA0 >> 2, aS0 = cA0 & 3;
    int aR1 = cA1 >> 2, aS1 = cA1 & 3;
    int bR0 = cA0 >> 4, bS0 = cA0 & 15;
    int bR1 = cA1 >> 4, bS1 = cA1 & 15;
    const __nv_bfloat16* gA0 = g_wt + (size_t)(m0 + aR0) * 256 + aS0 * 8;
    const __nv_bfloat16* gA1 = g_wt + (size_t)(m0 + aR1) * 256 + aS1 * 8;
    const __nv_bfloat16* gB0 = g_xh + ((size_t)b * 256 + bR0) * NPOS + n0 + bS0 * 8;
    const __nv_bfloat16* gB1 = g_xh + ((size_t)b * 256 + bR1) * NPOS + n0 + bS1 * 8;
    uint32_t dA0 = aR0 * 80 + aS0 * 16, dA1 = aR1 * 80 + aS1 * 16;
    uint32_t dB0 = 10240 + bR0 * 272 + bS0 * 16, dB1 = 10240 + bR1 * 272 + bS1 * 16;

#define LOADSTAGE(s, k0)                                                   \
    {                                                                      \
        uint32_t stb = sb + (s) * QST;                                     \
        cpa16(stb + dA0, gA0 + (k0));                                      \
        cpa16(stb + dA1, gA1 + (k0));                                      \
        cpa16(stb + dB0, gB0 + (size_t)(k0) * NPOS);                       \
        cpa16(stb + dB1, gB1 + (size_t)(k0) * NPOS);                       \
        CPA_COMMIT();                                                      \
    }

    uint32_t aOff = (uint32_t)(wr * 64 + (lane & 15)) * 80 + ((lane >> 4) << 3) * 2;
    uint32_t bOff = 10240 + (uint32_t)(((lane >> 3) & 1) * 8 + (lane & 7)) * 272 +
                    (uint32_t)(wc * 32 + ((lane >> 4) << 3)) * 2;

    LOADSTAGE(0, 0);
    LOADSTAGE(1, 32);
    LOADSTAGE(2, 64);

    for (int kk = 0; kk < 8; kk++) {
        int st = kk & 3;
        if (kk <= 5) { CPA_WAIT2(); } else if (kk == 6) { CPA_WAIT1(); } else { CPA_WAIT0(); }
        __syncthreads();
        if (kk + 3 < 8) LOADSTAGE((kk + 3) & 3, (kk + 3) * 32);
        uint32_t stb = sb + st * QST;
#pragma unroll
        for (int kh = 0; kh < 2; kh++) {
            uint32_t af[4][4];
#pragma unroll
            for (int mt = 0; mt < 4; mt++)
                ldm_x4(af[mt], stb + aOff + mt * 1280 + kh * 32);
            uint32_t bfr[4][2];
#pragma unroll
            for (int pr = 0; pr < 2; pr++) {
                uint32_t r0, r1, r2, r3;
                ldm_x4t(r0, r1, r2, r3, stb + bOff + kh * 4352 + pr * 32);
                bfr[2 * pr][0] = r0; bfr[2 * pr][1] = r1;
                bfr[2 * pr + 1][0] = r2; bfr[2 * pr + 1][1] = r3;
            }
#pragma unroll
            for (int mt = 0; mt < 4; mt++)
#pragma unroll
                for (int nt = 0; nt < 4; nt++) mma_bf16(acc[mt][nt], af[mt], bfr[nt]);
        }
    }

    const float* fb = g_film + b * 512;
    __nv_bfloat16* C = g_qkvh + (size_t)b * 384 * NPOS;
#pragma unroll
    for (int mt = 0; mt < 4; mt++) {
        int mA = m0 + wr * 64 + mt * 16 + lq;
        int mB = mA + 8;
        float aA, bA, aB, bB;
        filmAB(mA, fb, aA, bA);
        filmAB(mB, fb, aB, bB);
#pragma unroll
        for (int nt = 0; nt < 4; nt++) {
            int cc = n0 + wc * 32 + nt * 8 + 2 * lr;
            __nv_bfloat162 o0 = __floats2bfloat162_rn(fmaf(aA, acc[mt][nt][0], bA),
                                                      fmaf(aA, acc[mt][nt][1], bA));
            __nv_bfloat162 o1 = __floats2bfloat162_rn(fmaf(aB, acc[mt][nt][2], bB),
                                                      fmaf(aB, acc[mt][nt][3], bB));
            *(__nv_bfloat162*)&C[(size_t)mA * NPOS + cc] = o0;
            *(__nv_bfloat162*)&C[(size_t)mB * NPOS + cc] = o1;
        }
    }
}

// ================= ctx via mma: no-max exp, S = E @ V^T (R10 version) =================
#define KSE 520
__global__ void __launch_bounds__(256) ctx_mma() {
    extern __shared__ __nv_bfloat16 cs[];
    __nv_bfloat16* Ks = cs;
    __nv_bfloat16* Vs = cs + 32 * KSE;

    int b = blockIdx.z, h = blockIdx.y, chunk = blockIdx.x;
    int t = threadIdx.x;

    const __nv_bfloat16* Kg = g_qkvh + ((size_t)b * 384 + 128 + h * 32) * NPOS + chunk * 512;
    const __nv_bfloat16* Vg = Kg + (size_t)128 * NPOS;
    for (int i = t; i < 2048; i += 256) {
        int row = i >> 6, col = i & 63;
        *(uint4*)&Ks[row * KSE + col * 8] = *(const uint4*)(Kg + (size_t)row * NPOS + col * 8);
        *(uint4*)&Vs[row * KSE + col * 8] = *(const uint4*)(Vg + (size_t)row * NPOS + col * 8);
    }
    __syncthreads();

    int c = t >> 3, sub = t & 7;
    __nv_bfloat16* Kr = Ks + c * KSE + sub * 64;
    float z = 0.f;
#pragma unroll
    for (int j4 = 0; j4 < 8; j4++) {
        uint4 kv = *(uint4*)&Kr[j4 * 8];
        __nv_bfloat162* kp = (__nv_bfloat162*)&kv;
        uint4 ev;
        __nv_bfloat162* ep = (__nv_bfloat162*)&ev;
#pragma unroll
        for (int p = 0; p < 4; p++) {
            float2 f = __bfloat1622float2(kp[p]);
            __nv_bfloat162 e2 = __floats2bfloat162_rn(__expf(f.x), __expf(f.y));
            ep[p] = e2;
            float2 ef = __bfloat1622float2(e2);
            z += ef.x + ef.y;
        }
        *(uint4*)&Kr[j4 * 8] = ev;
    }
#pragma unroll
    for (int o = 1; o < 8; o <<= 1) z += __shfl_xor_sync(0xffffffffu, z, o);
    if (sub == 0) g_Zp[((size_t)chunk * NB + b) * 128 + h * 32 + c] = z;
    __syncthreads();

    int w = t >> 5, lane = t & 31;
    int mrow = (w & 1) * 16, ncol = (w >> 1) * 8;
    uint32_t Eb = smem_u32(Ks), Vb = smem_u32(Vs);
    uint32_t aAddr = Eb + ((mrow + (lane & 15)) * KSE + ((lane >> 4) << 3)) * 2;
    uint32_t bAddr = Vb + ((ncol + (lane & 7)) * KSE + (((lane >> 3) & 3) << 3)) * 2;
    float acc[4] = {0.f, 0.f, 0.f, 0.f};
#pragma unroll 8
    for (int ks = 0; ks < 32; ks++) {
        uint32_t a[4], bb[2];
        ldm_x4(a, aAddr + ks * 32);
        ldm_x2(bb, bAddr + ks * 32);
        mma_bf16(acc, a, bb);
    }
    int lq = lane >> 2, lr = lane & 3;
    float* Sp = g_Sp + (((size_t)chunk * NB + b) * 4 + h) * 1024;
    Sp[(mrow + lq) * 32 + ncol + 2 * lr] = acc[0];
    Sp[(mrow + lq) * 32 + ncol + 2 * lr + 1] = acc[1];
    Sp[(mrow + lq + 8) * 32 + ncol + 2 * lr] = acc[2];
    Sp[(mrow + lq + 8) * 32 + ncol + 2 * lr + 1] = acc[3];
}

// ---------------- ctxnorm: combine chunks + normalize -> g_ctx (128 CTAs) ----------------
__global__ void ctxnorm_kernel() {
    int seg = blockIdx.x, b = blockIdx.y, t = threadIdx.x;
    __shared__ float zs[16];
    if (t < 16) {
        int chan = seg * 16 + t;
        float zz = 0.f;
#pragma unroll
        for (int ch = 0; ch < NCHUNK; ch++) zz += g_Zp[((size_t)ch * NB + b) * 128 + chan];
        zs[t] = zz;
    }
    __syncthreads();
#pragma unroll
    for (int rep = 0; rep < 2; rep++) {
        int i = seg * 512 + rep * 256 + t;
        float s = 0.f;
#pragma unroll
        for (int ch = 0; ch < NCHUNK; ch++) s += g_Sp[((size_t)ch * NB + b) * 4096 + i];
        g_ctx[b * 4096 + i] = s / zs[(i >> 5) - seg * 16];
    }
}

// ---------------- buildM2: M rows from g_ctx (256 CTAs, 16 rows each) ----------------
__global__ void buildM2_kernel(const float* __restrict__ Wout) {
    int rowseg = blockIdx.x, b = blockIdx.y, t = threadIdx.x;
    __shared__ float ctxs[4096];
    const float4* Cg = (const float4*)(g_ctx + b * 4096);
#pragma unroll
    for (int j = 0; j < 4; j++) {
        int i = t + 256 * j;
        *(float4*)&ctxs[i * 4] = Cg[i];
    }
    __syncthreads();
    int row = rowseg * 16 + (t >> 4);
    int sub = t & 15;
    int c0 = sub * 8;             // 8 outputs, all within one head group
    int g = c0 >> 5;
    const float* wr = Wout + row * 128 + g * 32;
    float wv[32];
#pragma unroll
    for (int e = 0; e < 32; e++) wv[e] = wr[e];
    __nv_bfloat16* Mr = g_Mb + (size_t)b * 32768 + row * 128;
#pragma unroll
    for (int j = 0; j < 8; j++) {
        int c = c0 + j;
        int c2 = c & 31;
        float s = 0.f;
#pragma unroll
        for (int e = 0; e < 32; e++) s += wv[e] * ctxs[g * 1024 + c2 * 32 + e];
        Mr[c] = __float2bfloat16(s);
    }
}

// ---------------- final v3 (R10 version, unchanged) ----------------
#define KW2 72
#define FO_M   0               // 256*72 = 18432 words
#define FO_Q   18432           // 128*72 = 9216 words
#define FO_B   27648
#define FO_G   27904
#define FO_WS  28160           // 16*32
#define FO_WQ  28672
#define FO_CS  29184           // 128
#define FO_CQ  29312
#define F_TOT  29440           // words = 117760 bytes

__global__ void __launch_bounds__(512) final_mma(const float* __restrict__ bout,
                                                 const float* __restrict__ gam,
                                                 float* __restrict__ out) {
    extern __shared__ uint32_t fsm[];
    uint32_t* Msm = fsm + FO_M;
    uint32_t* Qsm = fsm + FO_Q;
    float* bsm = (float*)(fsm + FO_B);
    float* gsm = (float*)(fsm + FO_G);
    float* wsum = (float*)(fsm + FO_WS);
    float* wsq = (float*)(fsm + FO_WQ);
    float* csum = (float*)(fsm + FO_CS);
    float* csq = (float*)(fsm + FO_CQ);

    int b = blockIdx.y, n0 = blockIdx.x * 128, t = threadIdx.x;
    int lane = t & 31, w = t >> 5;
    int wm = w >> 2, wn = w & 3;
    int lq = lane >> 2, lr = lane & 3;

    const __nv_bfloat16* Mg = g_Mb + (size_t)b * 32768;
#pragma unroll
    for (int j = 0; j < 8; j++) {
        int c = t + 512 * j;
        int row = c >> 4, seg = c & 15;
        cpa16(smem_u32(&Msm[row * KW2 + seg * 4]), Mg + row * 128 + seg * 8);
    }
    CPA_COMMIT();

    if (t < 256) {
        bsm[t] = bout[t];
        gsm[t] = gam[t];
    }

    {
        int h = t >> 7, col = t & 127;
        const __nv_bfloat16* Qc = g_qkvh + (size_t)b * 384 * NPOS + (size_t)(h * 32) * NPOS + n0 + col;
        float v[32];
        float ssum = 0.f;
#pragma unroll
        for (int i = 0; i < 32; i++) {
            v[i] = __expf(__bfloat162float(Qc[(size_t)i * NPOS]));
            ssum += v[i];
        }
        float inv = SCALE / ssum;
#pragma unroll
        for (int i2 = 0; i2 < 16; i2++) {
            __nv_bfloat162 p = __floats2bfloat162_rn(v[2 * i2] * inv, v[2 * i2 + 1] * inv);
            Qsm[col * KW2 + h * 16 + i2] = *(uint32_t*)&p;
        }
    }
    CPA_WAIT0();
    __syncthreads();

    float acc[4][4][4];
#pragma unroll
    for (int mt = 0; mt < 4; mt++)
#pragma unroll
        for (int nt = 0; nt < 4; nt++)
#pragma unroll
            for (int r = 0; r < 4; r++) acc[mt][nt][r] = 0.0f;

#pragma unroll
    for (int ks = 0; ks < 8; ks++) {
        int ksw = ks * 8;
        uint32_t af[4][4], bfr[4][2];
#pragma unroll
        for (int mt = 0; mt < 4; mt++) {
            int r0 = wm * 64 + mt * 16 + lq;
            af[mt][0] = Msm[r0 * KW2 + ksw + lr];
            af[mt][1] = Msm[(r0 + 8) * KW2 + ksw + lr];
            af[mt][2] = Msm[r0 * KW2 + ksw + lr + 4];
            af[mt][3] = Msm[(r0 + 8) * KW2 + ksw + lr + 4];
        }
#pragma unroll
        for (int nt = 0; nt < 4; nt++) {
            int n = wn * 32 + nt * 8 + lq;
            bfr[nt][0] = Qsm[n * KW2 + ksw + lr];
            bfr[nt][1] = Qsm[n * KW2 + ksw + lr + 4];
        }
#pragma unroll
        for (int mt = 0; mt < 4; mt++)
#pragma unroll
            for (int nt = 0; nt < 4; nt++) mma_bf16(acc[mt][nt], af[mt], bfr[nt]);
    }

    float ps[4][2], pq[4][2];
#pragma unroll
    for (int nt = 0; nt < 4; nt++)
#pragma unroll
        for (int j = 0; j < 2; j++) { ps[nt][j] = 0.f; pq[nt][j] = 0.f; }
#pragma unroll
    for (int mt = 0; mt < 4; mt++) {
        float b0v = bsm[wm * 64 + mt * 16 + lq];
        float b1v = bsm[wm * 64 + mt * 16 + lq + 8];
#pragma unroll
        for (int nt = 0; nt < 4; nt++) {
            acc[mt][nt][0] += b0v; acc[mt][nt][1] += b0v;
            acc[mt][nt][2] += b1v; acc[mt][nt][3] += b1v;
#pragma unroll
            for (int j = 0; j < 2; j++) {
                float v0 = acc[mt][nt][j], v1 = acc[mt][nt][2 + j];
                ps[nt][j] += v0 + v1;
                pq[nt][j] += v0 * v0 + v1 * v1;
            }
        }
    }
#pragma unroll
    for (int nt = 0; nt < 4; nt++)
#pragma unroll
        for (int j = 0; j < 2; j++) {
#pragma unroll
            for (int o = 4; o <= 16; o <<= 1) {
                ps[nt][j] += __shfl_xor_sync(0xffffffffu, ps[nt][j], o);
                pq[nt][j] += __shfl_xor_sync(0xffffffffu, pq[nt][j], o);
            }
        }
    if (lq == 0) {
#pragma unroll
        for (int nt = 0; nt < 4; nt++)
#pragma unroll
            for (int j = 0; j < 2; j++) {
                wsum[w * 32 + nt * 8 + 2 * lr + j] = ps[nt][j];
                wsq[w * 32 + nt * 8 + 2 * lr + j] = pq[nt][j];
            }
    }
    __syncthreads();
    if (t < 128) {
        int wnc = t >> 5, cl = t & 31;
        float sx = 0.f, sq2 = 0.f;
#pragma unroll
        for (int k = 0; k < 4; k++) {
            sx += wsum[(k * 4 + wnc) * 32 + cl];
            sq2 += wsq[(k * 4 + wnc) * 32 + cl];
        }
        csum[t] = sx;
        csq[t] = sq2;
    }
    __syncthreads();

    float mean[4][2], rs[4][2];
#pragma unroll
    for (int nt = 0; nt < 4; nt++)
#pragma unroll
        for (int j = 0; j < 2; j++) {
            int cg = wn * 32 + nt * 8 + 2 * lr + j;
            float mu = csum[cg] * (1.0f / 256.0f);
            float var = csq[cg] * (1.0f / 256.0f) - mu * mu;
            mean[nt][j] = mu;
            rs[nt][j] = rsqrtf(var + 1e-5f);
        }
#pragma unroll
    for (int mt = 0; mt < 4; mt++) {
        int r0 = wm * 64 + mt * 16 + lq;
        float g0 = gsm[r0], g1 = gsm[r0 + 8];
#pragma unroll
        for (int nt = 0; nt < 4; nt++) {
            int cc = n0 + wn * 32 + nt * 8 + 2 * lr;
            float2 o0, o1;
            o0.x = (acc[mt][nt][0] - mean[nt][0]) * rs[nt][0] * g0;
            o0.y = (acc[mt][nt][1] - mean[nt][1]) * rs[nt][1] * g0;
            o1.x = (acc[mt][nt][2] - mean[nt][0]) * rs[nt][0] * g1;
            o1.y = (acc[mt][nt][3] - mean[nt][1]) * rs[nt][1] * g1;
            *(float2*)&out[((size_t)(b * 256 + r0)) * NPOS + cc] = o0;
            *(float2*)&out[((size_t)(b * 256 + r0 + 8)) * NPOS + cc] = o1;
        }
    }
}

// ---------------- launch ----------------
extern "C" void kernel_launch(void* const* d_in, const int* in_sizes, int n_in,
                              void* d_out, int out_size) {
    (void)in_sizes; (void)n_in; (void)out_size;
    const float* x = (const float*)d_in[0];
    const float* cond = (const float*)d_in[1];
    const float* W_qkv = (const float*)d_in[2];
    const float* W_cond = (const float*)d_in[3];
    const float* b_cond = (const float*)d_in[4];
    const float* W_out = (const float*)d_in[5];
    const float* b_out = (const float*)d_in[6];
    const float* g = (const float*)d_in[7];
    float* out = (float*)d_out;

    film_kernel<<<NB, 512>>>(cond, W_cond, b_cond);
    wconv_kernel<<<96, 1024>>>(W_qkv);
    xconv_kernel<<<(NB * 256 * NPOS) / 1024, 256>>>(x);

    cudaFuncSetAttribute(qkv_mma, cudaFuncAttributeMaxDynamicSharedMemorySize, QKV_SMEM);
    qkv_mma<<<dim3(3, 32, NB), 256, QKV_SMEM>>>();

    int ctx_smem = 2 * 32 * KSE * (int)sizeof(__nv_bfloat16);
    cudaFuncSetAttribute(ctx_mma, cudaFuncAttributeMaxDynamicSharedMemorySize, ctx_smem);
    ctx_mma<<<dim3(NCHUNK, 4, NB), 256, ctx_smem>>>();

    ctxnorm_kernel<<<dim3(8, NB), 256>>>();
    buildM2_kernel<<<dim3(16, NB), 256>>>(W_out);

    int smbytes = F_TOT * (int)sizeof(uint32_t);
    cudaFuncSetAttribute(final_mma, cudaFuncAttributeMaxDynamicSharedMemorySize, smbytes);
    final_mma<<<dim3(32, NB), 512, smbytes>>>(b_out, g, out);
}

// round 15
// speedup vs baseline: 1.2669x; 1.0371x over previous
#include <cuda_runtime.h>
#include <cuda_bf16.h>
#include <cstdint>

#define NB 16
#define NPOS 4096
#define SCALE 0.17677669529663687f   // 32^-0.5
#define INVN (1.0f / 4096.0f)
#define NCHUNK 8

// ---------------- scratch (device globals; no runtime allocation) ----------------
__device__ __nv_bfloat16 g_qkvh[(size_t)NB * 384 * NPOS]; // q(raw)/k(FiLM)/v(FiLM,/n) bf16
__device__ __nv_bfloat16 g_xh[(size_t)NB * 256 * NPOS];   // X bf16, same [b][k][n] layout
__device__ float g_film[NB * 512];
__device__ float g_Sp[NCHUNK * NB * 4 * 32 * 32];
__device__ float g_Zp[NCHUNK * NB * 128];
__device__ float g_ctx[NB * 4096];                        // normalized context per batch
__device__ __nv_bfloat16 g_Mb[NB * 256 * 128];            // M_b bf16, k contiguous
__device__ __nv_bfloat16 g_wt[384 * 256];                 // W_qkv bf16, k contiguous

// ---------------- FiLM ----------------
__global__ void film_kernel(const float* __restrict__ cond,
                            const float* __restrict__ Wc,
                            const float* __restrict__ bc) {
    int b = blockIdx.x, t = threadIdx.x;
    __shared__ float sc[256];
    if (t < 256) {
        float xv = cond[b * 256 + t];
        sc[t] = xv / (1.0f + __expf(-xv));
    }
    __syncthreads();
    const float* wr = Wc + t * 256;
    float acc = bc[t];
#pragma unroll 8
    for (int j = 0; j < 256; j++) acc += wr[j] * sc[j];
    g_film[b * 512 + t] = acc;
}

__global__ void wconv_kernel(const float* __restrict__ W) {
    int i = blockIdx.x * 1024 + threadIdx.x;
    if (i < 384 * 256) g_wt[i] = __float2bfloat16(W[i]);
}

// X fp32 -> bf16, identity layout, vectorized
__global__ void xconv_kernel(const float* __restrict__ X) {
    size_t i = ((size_t)blockIdx.x * 256 + threadIdx.x) * 4;
    float4 v = *(const float4*)(X + i);
    __nv_bfloat162 p0 = __floats2bfloat162_rn(v.x, v.y);
    __nv_bfloat162 p1 = __floats2bfloat162_rn(v.z, v.w);
    uint2 u;
    u.x = *(uint32_t*)&p0;
    u.y = *(uint32_t*)&p1;
    *(uint2*)(g_xh + i) = u;
}

// ================= helpers =================
__device__ __forceinline__ uint32_t smem_u32(const void* p) {
    uint32_t a;
    asm("{ .reg .u64 t; cvta.to.shared.u64 t, %1; cvt.u32.u64 %0, t; }" : "=r"(a) : "l"(p));
    return a;
}
__device__ __forceinline__ void cpa16(uint32_t dst, const void* src) {
    asm volatile("cp.async.cg.shared.global [%0], [%1], 16;"
                 :: "r"(dst), "l"(__cvta_generic_to_global(src)));
}
#define CPA_COMMIT() asm volatile("cp.async.commit_group;" ::: "memory")
#define CPA_WAIT0()  asm volatile("cp.async.wait_group 0;" ::: "memory")
#define CPA_WAIT1()  asm volatile("cp.async.wait_group 1;" ::: "memory")

__device__ __forceinline__ void mma_bf16(float c[4], const uint32_t a[4], const uint32_t b[2]) {
    asm volatile(
        "mma.sync.aligned.m16n8k16.row.col.f32.bf16.bf16.f32 "
        "{%0,%1,%2,%3}, {%4,%5,%6,%7}, {%8,%9}, {%0,%1,%2,%3};\n"
        : "+f"(c[0]), "+f"(c[1]), "+f"(c[2]), "+f"(c[3])
        : "r"(a[0]), "r"(a[1]), "r"(a[2]), "r"(a[3]), "r"(b[0]), "r"(b[1]));
}
__device__ __forceinline__ void ldm_x4(uint32_t r[4], uint32_t addr) {
    asm volatile("ldmatrix.sync.aligned.m8n8.x4.shared.b16 {%0,%1,%2,%3}, [%4];"
                 : "=r"(r[0]), "=r"(r[1]), "=r"(r[2]), "=r"(r[3]) : "r"(addr));
}
__device__ __forceinline__ void ldm_x2(uint32_t r[2], uint32_t addr) {
    asm volatile("ldmatrix.sync.aligned.m8n8.x2.shared.b16 {%0,%1}, [%2];"
                 : "=r"(r[0]), "=r"(r[1]) : "r"(addr));
}
__device__ __forceinline__ void ldm_x4t(uint32_t& r0, uint32_t& r1, uint32_t& r2, uint32_t& r3,
                                        uint32_t addr) {
    asm volatile("ldmatrix.sync.aligned.m8n8.x4.trans.shared.b16 {%0,%1,%2,%3}, [%4];"
                 : "=r"(r0), "=r"(r1), "=r"(r2), "=r"(r3) : "r"(addr));
}
__device__ __forceinline__ void filmAB(int m, const float* __restrict__ fb,
                                       float& alpha, float& beta) {
    alpha = 1.0f; beta = 0.0f;
    if (m >= 256) {
        int c = m - 256;
        alpha = (1.0f + fb[256 + c]) * INVN;
        beta = fb[384 + c] * INVN;
    } else if (m >= 128) {
        int c = m - 128;
        alpha = 1.0f + fb[c];
        beta = fb[128 + c];
    }
}

// ================= qkv GEMM: 3-stage cp.async, 64-k stages =================
// A: 128 rows x 64 k bf16, row stride 144B (36 words, conflict-free ldmatrix).
// B: 64 rows x 128 n bf16, row stride 272B. Stage = 18432 + 17408 = 35840 B.
#define QST 35840
#define QKV_SMEM (3 * QST)

__global__ void __launch_bounds__(256, 2) qkv_mma(void) {
    extern __shared__ uint8_t qs[];
    uint32_t sb = smem_u32(qs);

    int b = blockIdx.z, grp = blockIdx.x;
    int m0 = grp * 128, n0 = blockIdx.y * 128;
    int t = threadIdx.x, lane = t & 31, w = t >> 5;
    int wr = w >> 2, wc = w & 3;
    int lq = lane >> 2, lr = lane & 3;

    float acc[4][4][4];
#pragma unroll
    for (int mt = 0; mt < 4; mt++)
#pragma unroll
        for (int nt = 0; nt < 4; nt++)
#pragma unroll
            for (int r = 0; r < 4; r++) acc[mt][nt][r] = 0.0f;

    // base chunk mapping (j-th chunk = base + fixed stride)
    int rA = t >> 3, sA = t & 7;           // A: 128 rows x 8 chunks
    int rB = t >> 4, sB = t & 15;          // B: 64 rows x 16 chunks (j adds 16 rows)
    const __nv_bfloat16* gA0 = g_wt + (size_t)(m0 + rA) * 256 + sA * 8;
    const __nv_bfloat16* gB0 = g_xh + ((size_t)b * 256 + rB) * NPOS + n0 + sB * 8;
    uint32_t dA0 = rA * 144 + sA * 16;
    uint32_t dB0 = 18432 + rB * 272 + sB * 16;

#define LOADSTAGE(s, k0)                                                        \
    {                                                                           \
        uint32_t stb = sb + (s) * QST;                                          \
        _Pragma("unroll")                                                       \
        for (int j = 0; j < 4; j++) {                                           \
            cpa16(stb + dA0 + 4608 * j, gA0 + (k0) + 8192 * j);                 \
            cpa16(stb + dB0 + 4352 * j, gB0 + (size_t)((k0) + 16 * j) * NPOS);  \
        }                                                                       \
        CPA_COMMIT();                                                           \
    }

    // fragment base offsets (bytes)
    uint32_t aOff = (uint32_t)(wr * 64 + (lane & 15)) * 144 + ((lane >> 4) << 3) * 2;
    uint32_t bOff = 18432 + (uint32_t)(((lane >> 3) & 1) * 8 + (lane & 7)) * 272 +
                    (uint32_t)(wc * 32 + ((lane >> 4) << 3)) * 2;

    LOADSTAGE(0, 0);
    LOADSTAGE(1, 64);

    for (int kk = 0; kk < 4; kk++) {
        int st = kk % 3;
        if (kk < 3) { CPA_WAIT1(); } else { CPA_WAIT0(); }
        __syncthreads();
        if (kk + 2 < 4) LOADSTAGE((kk + 2) % 3, (kk + 2) * 64);
        uint32_t stb = sb + st * QST;
#pragma unroll
        for (int kh = 0; kh < 4; kh++) {
            uint32_t af[4][4];
#pragma unroll
            for (int mt = 0; mt < 4; mt++)
                ldm_x4(af[mt], stb + aOff + mt * 2304 + kh * 32);
            uint32_t bfr[4][2];
#pragma unroll
            for (int pr = 0; pr < 2; pr++) {
                uint32_t r0, r1, r2, r3;
                ldm_x4t(r0, r1, r2, r3, stb + bOff + kh * 4352 + pr * 32);
                bfr[2 * pr][0] = r0; bfr[2 * pr][1] = r1;
                bfr[2 * pr + 1][0] = r2; bfr[2 * pr + 1][1] = r3;
            }
#pragma unroll
            for (int mt = 0; mt < 4; mt++)
#pragma unroll
                for (int nt = 0; nt < 4; nt++) mma_bf16(acc[mt][nt], af[mt], bfr[nt]);
        }
    }

    const float* fb = g_film + b * 512;
    __nv_bfloat16* C = g_qkvh + (size_t)b * 384 * NPOS;
#pragma unroll
    for (int mt = 0; mt < 4; mt++) {
        int mA = m0 + wr * 64 + mt * 16 + lq;
        int mB = mA + 8;
        float aA, bA, aB, bB;
        filmAB(mA, fb, aA, bA);
        filmAB(mB, fb, aB, bB);
#pragma unroll
        for (int nt = 0; nt < 4; nt++) {
            int cc = n0 + wc * 32 + nt * 8 + 2 * lr;
            __nv_bfloat162 o0 = __floats2bfloat162_rn(fmaf(aA, acc[mt][nt][0], bA),
                                                      fmaf(aA, acc[mt][nt][1], bA));
            __nv_bfloat162 o1 = __floats2bfloat162_rn(fmaf(aB, acc[mt][nt][2], bB),
                                                      fmaf(aB, acc[mt][nt][3], bB));
            *(__nv_bfloat162*)&C[(size_t)mA * NPOS + cc] = o0;
            *(__nv_bfloat162*)&C[(size_t)mB * NPOS + cc] = o1;
        }
    }
}

// ================= ctx via mma: no-max exp, dual accumulator chains =================
#define KSE 520
__global__ void __launch_bounds__(256) ctx_mma() {
    extern __shared__ __nv_bfloat16 cs[];
    __nv_bfloat16* Ks = cs;
    __nv_bfloat16* Vs = cs + 32 * KSE;

    int b = blockIdx.z, h = blockIdx.y, chunk = blockIdx.x;
    int t = threadIdx.x;

    const __nv_bfloat16* Kg = g_qkvh + ((size_t)b * 384 + 128 + h * 32) * NPOS + chunk * 512;
    const __nv_bfloat16* Vg = Kg + (size_t)128 * NPOS;
    for (int i = t; i < 2048; i += 256) {
        int row = i >> 6, col = i & 63;
        *(uint4*)&Ks[row * KSE + col * 8] = *(const uint4*)(Kg + (size_t)row * NPOS + col * 8);
        *(uint4*)&Vs[row * KSE + col * 8] = *(const uint4*)(Vg + (size_t)row * NPOS + col * 8);
    }
    __syncthreads();

    int c = t >> 3, sub = t & 7;
    __nv_bfloat16* Kr = Ks + c * KSE + sub * 64;
    float z = 0.f;
#pragma unroll
    for (int j4 = 0; j4 < 8; j4++) {
        uint4 kv = *(uint4*)&Kr[j4 * 8];
        __nv_bfloat162* kp = (__nv_bfloat162*)&kv;
        uint4 ev;
        __nv_bfloat162* ep = (__nv_bfloat162*)&ev;
#pragma unroll
        for (int p = 0; p < 4; p++) {
            float2 f = __bfloat1622float2(kp[p]);
            __nv_bfloat162 e2 = __floats2bfloat162_rn(__expf(f.x), __expf(f.y));
            ep[p] = e2;
            float2 ef = __bfloat1622float2(e2);
            z += ef.x + ef.y;
        }
        *(uint4*)&Kr[j4 * 8] = ev;
    }
#pragma unroll
    for (int o = 1; o < 8; o <<= 1) z += __shfl_xor_sync(0xffffffffu, z, o);
    if (sub == 0) g_Zp[((size_t)chunk * NB + b) * 128 + h * 32 + c] = z;
    __syncthreads();

    // S(32x32) = E @ V^T, dual chains for ILP
    int w = t >> 5, lane = t & 31;
    int mrow = (w & 1) * 16, ncol = (w >> 1) * 8;
    uint32_t Eb = smem_u32(Ks), Vb = smem_u32(Vs);
    uint32_t aAddr = Eb + ((mrow + (lane & 15)) * KSE + ((lane >> 4) << 3)) * 2;
    uint32_t bAddr = Vb + ((ncol + (lane & 7)) * KSE + (((lane >> 3) & 3) << 3)) * 2;
    float acc0[4] = {0.f, 0.f, 0.f, 0.f};
    float acc1[4] = {0.f, 0.f, 0.f, 0.f};
#pragma unroll
    for (int ks = 0; ks < 32; ks += 2) {
        uint32_t a0[4], b0[2], a1[4], b1[2];
        ldm_x4(a0, aAddr + ks * 32);
        ldm_x2(b0, bAddr + ks * 32);
        ldm_x4(a1, aAddr + ks * 32 + 32);
        ldm_x2(b1, bAddr + ks * 32 + 32);
        mma_bf16(acc0, a0, b0);
        mma_bf16(acc1, a1, b1);
    }
    int lq = lane >> 2, lr = lane & 3;
    float* Sp = g_Sp + (((size_t)chunk * NB + b) * 4 + h) * 1024;
    Sp[(mrow + lq) * 32 + ncol + 2 * lr] = acc0[0] + acc1[0];
    Sp[(mrow + lq) * 32 + ncol + 2 * lr + 1] = acc0[1] + acc1[1];
    Sp[(mrow + lq + 8) * 32 + ncol + 2 * lr] = acc0[2] + acc1[2];
    Sp[(mrow + lq + 8) * 32 + ncol + 2 * lr + 1] = acc0[3] + acc1[3];
}

// ---------------- ctxnorm: combine chunks + normalize -> g_ctx (128 CTAs) ----------------
__global__ void ctxnorm_kernel() {
    int seg = blockIdx.x, b = blockIdx.y, t = threadIdx.x;
    __shared__ float zs[16];
    if (t < 16) {
        int chan = seg * 16 + t;
        float zz = 0.f;
#pragma unroll
        for (int ch = 0; ch < NCHUNK; ch++) zz += g_Zp[((size_t)ch * NB + b) * 128 + chan];
        zs[t] = zz;
    }
    __syncthreads();
#pragma unroll
    for (int rep = 0; rep < 2; rep++) {
        int i = seg * 512 + rep * 256 + t;
        float s = 0.f;
#pragma unroll
        for (int ch = 0; ch < NCHUNK; ch++) s += g_Sp[((size_t)ch * NB + b) * 4096 + i];
        g_ctx[b * 4096 + i] = s / zs[(i >> 5) - seg * 16];
    }
}

// ---------------- buildM2: M rows from g_ctx (256 CTAs, 16 rows each) ----------------
__global__ void buildM2_kernel(const float* __restrict__ Wout) {
    int rowseg = blockIdx.x, b = blockIdx.y, t = threadIdx.x;
    __shared__ float ctxs[4096];
    const float4* Cg = (const float4*)(g_ctx + b * 4096);
#pragma unroll
    for (int j = 0; j < 4; j++) {
        int i = t + 256 * j;
        *(float4*)&ctxs[i * 4] = Cg[i];
    }
    __syncthreads();
    int row = rowseg * 16 + (t >> 4);
    int sub = t & 15;
    int c0 = sub * 8;
    int g = c0 >> 5;
    const float* wr = Wout + row * 128 + g * 32;
    float wv[32];
#pragma unroll
    for (int e = 0; e < 32; e++) wv[e] = wr[e];
    __nv_bfloat16* Mr = g_Mb + (size_t)b * 32768 + row * 128;
#pragma unroll
    for (int j = 0; j < 8; j++) {
        int c = c0 + j;
        int c2 = c & 31;
        float s = 0.f;
#pragma unroll
        for (int e = 0; e < 32; e++) s += wv[e] * ctxs[g * 1024 + c2 * 32 + e];
        Mr[c] = __float2bfloat16(s);
    }
}

// ---------------- final v3 (R10/R12 version, unchanged) ----------------
#define KW2 72
#define FO_M   0
#define FO_Q   18432
#define FO_B   27648
#define FO_G   27904
#define FO_WS  28160
#define FO_WQ  28672
#define FO_CS  29184
#define FO_CQ  29312
#define F_TOT  29440

__global__ void __launch_bounds__(512) final_mma(const float* __restrict__ bout,
                                                 const float* __restrict__ gam,
                                                 float* __restrict__ out) {
    extern __shared__ uint32_t fsm[];
    uint32_t* Msm = fsm + FO_M;
    uint32_t* Qsm = fsm + FO_Q;
    float* bsm = (float*)(fsm + FO_B);
    float* gsm = (float*)(fsm + FO_G);
    float* wsum = (float*)(fsm + FO_WS);
    float* wsq = (float*)(fsm + FO_WQ);
    float* csum = (float*)(fsm + FO_CS);
    float* csq = (float*)(fsm + FO_CQ);

    int b = blockIdx.y, n0 = blockIdx.x * 128, t = threadIdx.x;
    int lane = t & 31, w = t >> 5;
    int wm = w >> 2, wn = w & 3;
    int lq = lane >> 2, lr = lane & 3;

    const __nv_bfloat16* Mg = g_Mb + (size_t)b * 32768;
#pragma unroll
    for (int j = 0; j < 8; j++) {
        int c = t + 512 * j;
        int row = c >> 4, seg = c & 15;
        cpa16(smem_u32(&Msm[row * KW2 + seg * 4]), Mg + row * 128 + seg * 8);
    }
    CPA_COMMIT();

    if (t < 256) {
        bsm[t] = bout[t];
        gsm[t] = gam[t];
    }

    {
        int h = t >> 7, col = t & 127;
        const __nv_bfloat16* Qc = g_qkvh + (size_t)b * 384 * NPOS + (size_t)(h * 32) * NPOS + n0 + col;
        float v[32];
        float ssum = 0.f;
#pragma unroll
        for (int i = 0; i < 32; i++) {
            v[i] = __expf(__bfloat162float(Qc[(size_t)i * NPOS]));
            ssum += v[i];
        }
        float inv = SCALE / ssum;
#pragma unroll
        for (int i2 = 0; i2 < 16; i2++) {
            __nv_bfloat162 p = __floats2bfloat162_rn(v[2 * i2] * inv, v[2 * i2 + 1] * inv);
            Qsm[col * KW2 + h * 16 + i2] = *(uint32_t*)&p;
        }
    }
    CPA_WAIT0();
    __syncthreads();

    float acc[4][4][4];
#pragma unroll
    for (int mt = 0; mt < 4; mt++)
#pragma unroll
        for (int nt = 0; nt < 4; nt++)
#pragma unroll
            for (int r = 0; r < 4; r++) acc[mt][nt][r] = 0.0f;

#pragma unroll
    for (int ks = 0; ks < 8; ks++) {
        int ksw = ks * 8;
        uint32_t af[4][4], bfr[4][2];
#pragma unroll
        for (int mt = 0; mt < 4; mt++) {
            int r0 = wm * 64 + mt * 16 + lq;
            af[mt][0] = Msm[r0 * KW2 + ksw + lr];
            af[mt][1] = Msm[(r0 + 8) * KW2 + ksw + lr];
            af[mt][2] = Msm[r0 * KW2 + ksw + lr + 4];
            af[mt][3] = Msm[(r0 + 8) * KW2 + ksw + lr + 4];
        }
#pragma unroll
        for (int nt = 0; nt < 4; nt++) {
            int n = wn * 32 + nt * 8 + lq;
            bfr[nt][0] = Qsm[n * KW2 + ksw + lr];
            bfr[nt][1] = Qsm[n * KW2 + ksw + lr + 4];
        }
#pragma unroll
        for (int mt = 0; mt < 4; mt++)
#pragma unroll
            for (int nt = 0; nt < 4; nt++) mma_bf16(acc[mt][nt], af[mt], bfr[nt]);
    }

    float ps[4][2], pq[4][2];
#pragma unroll
    for (int nt = 0; nt < 4; nt++)
#pragma unroll
        for (int j = 0; j < 2; j++) { ps[nt][j] = 0.f; pq[nt][j] = 0.f; }
#pragma unroll
    for (int mt = 0; mt < 4; mt++) {
        float b0v = bsm[wm * 64 + mt * 16 + lq];
        float b1v = bsm[wm * 64 + mt * 16 + lq + 8];
#pragma unroll
        for (int nt = 0; nt < 4; nt++) {
            acc[mt][nt][0] += b0v; acc[mt][nt][1] += b0v;
            acc[mt][nt][2] += b1v; acc[mt][nt][3] += b1v;
#pragma unroll
            for (int j = 0; j < 2; j++) {
                float v0 = acc[mt][nt][j], v1 = acc[mt][nt][2 + j];
                ps[nt][j] += v0 + v1;
                pq[nt][j] += v0 * v0 + v1 * v1;
            }
        }
    }
#pragma unroll
    for (int nt = 0; nt < 4; nt++)
#pragma unroll
        for (int j = 0; j < 2; j++) {
#pragma unroll
            for (int o = 4; o <= 16; o <<= 1) {
                ps[nt][j] += __shfl_xor_sync(0xffffffffu, ps[nt][j], o);
                pq[nt][j] += __shfl_xor_sync(0xffffffffu, pq[nt][j], o);
            }
        }
    if (lq == 0) {
#pragma unroll
        for (int nt = 0; nt < 4; nt++)
#pragma unroll
            for (int j = 0; j < 2; j++) {
                wsum[w * 32 + nt * 8 + 2 * lr + j] = ps[nt][j];
                wsq[w * 32 + nt * 8 + 2 * lr + j] = pq[nt][j];
            }
    }
    __syncthreads();
    if (t < 128) {
        int wnc = t >> 5, cl = t & 31;
        float sx = 0.f, sq2 = 0.f;
#pragma unroll
        for (int k = 0; k < 4; k++) {
            sx += wsum[(k * 4 + wnc) * 32 + cl];
            sq2 += wsq[(k * 4 + wnc) * 32 + cl];
        }
        csum[t] = sx;
        csq[t] = sq2;
    }
    __syncthreads();

    float mean[4][2], rs[4][2];
#pragma unroll
    for (int nt = 0; nt < 4; nt++)
#pragma unroll
        for (int j = 0; j < 2; j++) {
            int cg = wn * 32 + nt * 8 + 2 * lr + j;
            float mu = csum[cg] * (1.0f / 256.0f);
            float var = csq[cg] * (1.0f / 256.0f) - mu * mu;
            mean[nt][j] = mu;
            rs[nt][j] = rsqrtf(var + 1e-5f);
        }
#pragma unroll
    for (int mt = 0; mt < 4; mt++) {
        int r0 = wm * 64 + mt * 16 + lq;
        float g0 = gsm[r0], g1 = gsm[r0 + 8];
#pragma unroll
        for (int nt = 0; nt < 4; nt++) {
            int cc = n0 + wn * 32 + nt * 8 + 2 * lr;
            float2 o0, o1;
            o0.x = (acc[mt][nt][0] - mean[nt][0]) * rs[nt][0] * g0;
            o0.y = (acc[mt][nt][1] - mean[nt][1]) * rs[nt][1] * g0;
            o1.x = (acc[mt][nt][2] - mean[nt][0]) * rs[nt][0] * g1;
            o1.y = (acc[mt][nt][3] - mean[nt][1]) * rs[nt][1] * g1;
            *(float2*)&out[((size_t)(b * 256 + r0)) * NPOS + cc] = o0;
            *(float2*)&out[((size_t)(b * 256 + r0 + 8)) * NPOS + cc] = o1;
        }
    }
}

// ---------------- launch ----------------
extern "C" void kernel_launch(void* const* d_in, const int* in_sizes, int n_in,
                              void* d_out, int out_size) {
    (void)in_sizes; (void)n_in; (void)out_size;
    const float* x = (const float*)d_in[0];
    const float* cond = (const float*)d_in[1];
    const float* W_qkv = (const float*)d_in[2];
    const float* W_cond = (const float*)d_in[3];
    const float* b_cond = (const float*)d_in[4];
    const float* W_out = (const float*)d_in[5];
    const float* b_out = (const float*)d_in[6];
    const float* g = (const float*)d_in[7];
    float* out = (float*)d_out;

    film_kernel<<<NB, 512>>>(cond, W_cond, b_cond);
    wconv_kernel<<<96, 1024>>>(W_qkv);
    xconv_kernel<<<(NB * 256 * NPOS) / 1024, 256>>>(x);

    cudaFuncSetAttribute(qkv_mma, cudaFuncAttributeMaxDynamicSharedMemorySize, QKV_SMEM);
    qkv_mma<<<dim3(3, 32, NB), 256, QKV_SMEM>>>();

    int ctx_smem = 2 * 32 * KSE * (int)sizeof(__nv_bfloat16);
    cudaFuncSetAttribute(ctx_mma, cudaFuncAttributeMaxDynamicSharedMemorySize, ctx_smem);
    ctx_mma<<<dim3(NCHUNK, 4, NB), 256, ctx_smem>>>();

    ctxnorm_kernel<<<dim3(8, NB), 256>>>();
    buildM2_kernel<<<dim3(16, NB), 256>>>(W_out);

    int smbytes = F_TOT * (int)sizeof(uint32_t);
    cudaFuncSetAttribute(final_mma, cudaFuncAttributeMaxDynamicSharedMemorySize, smbytes);
    final_mma<<<dim3(32, NB), 512, smbytes>>>(b_out, g, out);
}

// round 16
// speedup vs baseline: 1.2971x; 1.0238x over previous
#include <cuda_runtime.h>
#include <cuda_bf16.h>
#include <cstdint>

#define NB 16
#define NPOS 4096
#define SCALE 0.17677669529663687f   // 32^-0.5
#define INVN (1.0f / 4096.0f)
#define NCHUNK 8

// ---------------- scratch (device globals; no runtime allocation) ----------------
__device__ __nv_bfloat16 g_qkvh[(size_t)NB * 384 * NPOS]; // q(raw)/k(FiLM)/v(FiLM,/n) bf16
__device__ __nv_bfloat16 g_xh[(size_t)NB * 256 * NPOS];   // X bf16, same [b][k][n] layout
__device__ float g_film[NB * 512];
__device__ float g_Sp[NCHUNK * NB * 4 * 32 * 32];
__device__ float g_Zp[NCHUNK * NB * 128];
__device__ float g_ctx[NB * 4096];                        // normalized context per batch
__device__ __nv_bfloat16 g_Mb[NB * 256 * 128];            // M_b bf16, k contiguous
__device__ __nv_bfloat16 g_wt[384 * 256];                 // W_qkv bf16, k contiguous

// ---------------- FiLM ----------------
__global__ void film_kernel(const float* __restrict__ cond,
                            const float* __restrict__ Wc,
                            const float* __restrict__ bc) {
    int b = blockIdx.x, t = threadIdx.x;
    __shared__ float sc[256];
    if (t < 256) {
        float xv = cond[b * 256 + t];
        sc[t] = xv / (1.0f + __expf(-xv));
    }
    __syncthreads();
    const float* wr = Wc + t * 256;
    float acc = bc[t];
#pragma unroll 8
    for (int j = 0; j < 256; j++) acc += wr[j] * sc[j];
    g_film[b * 512 + t] = acc;
}

__global__ void wconv_kernel(const float* __restrict__ W) {
    int i = blockIdx.x * 1024 + threadIdx.x;
    if (i < 384 * 256) g_wt[i] = __float2bfloat16(W[i]);
}

// X fp32 -> bf16, identity layout, vectorized
__global__ void xconv_kernel(const float* __restrict__ X) {
    size_t i = ((size_t)blockIdx.x * 256 + threadIdx.x) * 4;
    float4 v = *(const float4*)(X + i);
    __nv_bfloat162 p0 = __floats2bfloat162_rn(v.x, v.y);
    __nv_bfloat162 p1 = __floats2bfloat162_rn(v.z, v.w);
    uint2 u;
    u.x = *(uint32_t*)&p0;
    u.y = *(uint32_t*)&p1;
    *(uint2*)(g_xh + i) = u;
}

// ================= helpers =================
__device__ __forceinline__ uint32_t smem_u32(const void* p) {
    uint32_t a;
    asm("{ .reg .u64 t; cvta.to.shared.u64 t, %1; cvt.u32.u64 %0, t; }" : "=r"(a) : "l"(p));
    return a;
}
__device__ __forceinline__ void cpa16(uint32_t dst, const void* src) {
    asm volatile("cp.async.cg.shared.global [%0], [%1], 16;"
                 :: "r"(dst), "l"(__cvta_generic_to_global(src)));
}
#define CPA_COMMIT() asm volatile("cp.async.commit_group;" ::: "memory")
#define CPA_WAIT0()  asm volatile("cp.async.wait_group 0;" ::: "memory")
#define CPA_WAIT1()  asm volatile("cp.async.wait_group 1;" ::: "memory")

__device__ __forceinline__ void mma_bf16(float c[4], const uint32_t a[4], const uint32_t b[2]) {
    asm volatile(
        "mma.sync.aligned.m16n8k16.row.col.f32.bf16.bf16.f32 "
        "{%0,%1,%2,%3}, {%4,%5,%6,%7}, {%8,%9}, {%0,%1,%2,%3};\n"
        : "+f"(c[0]), "+f"(c[1]), "+f"(c[2]), "+f"(c[3])
        : "r"(a[0]), "r"(a[1]), "r"(a[2]), "r"(a[3]), "r"(b[0]), "r"(b[1]));
}
__device__ __forceinline__ void ldm_x4(uint32_t r[4], uint32_t addr) {
    asm volatile("ldmatrix.sync.aligned.m8n8.x4.shared.b16 {%0,%1,%2,%3}, [%4];"
                 : "=r"(r[0]), "=r"(r[1]), "=r"(r[2]), "=r"(r[3]) : "r"(addr));
}
__device__ __forceinline__ void ldm_x2(uint32_t r[2], uint32_t addr) {
    asm volatile("ldmatrix.sync.aligned.m8n8.x2.shared.b16 {%0,%1}, [%2];"
                 : "=r"(r[0]), "=r"(r[1]) : "r"(addr));
}
__device__ __forceinline__ void ldm_x4t(uint32_t& r0, uint32_t& r1, uint32_t& r2, uint32_t& r3,
                                        uint32_t addr) {
    asm volatile("ldmatrix.sync.aligned.m8n8.x4.trans.shared.b16 {%0,%1,%2,%3}, [%4];"
                 : "=r"(r0), "=r"(r1), "=r"(r2), "=r"(r3) : "r"(addr));
}
__device__ __forceinline__ void filmAB(int m, const float* __restrict__ fb,
                                       float& alpha, float& beta) {
    alpha = 1.0f; beta = 0.0f;
    if (m >= 256) {
        int c = m - 256;
        alpha = (1.0f + fb[256 + c]) * INVN;
        beta = fb[384 + c] * INVN;
    } else if (m >= 128) {
        int c = m - 128;
        alpha = 1.0f + fb[c];
        beta = fb[128 + c];
    }
}

// ================= qkv GEMM: 3-stage cp.async, 64-k stages (R15, unchanged) ==========
#define QST 35840
#define QKV_SMEM (3 * QST)

__global__ void __launch_bounds__(256, 2) qkv_mma(void) {
    extern __shared__ uint8_t qs[];
    uint32_t sb = smem_u32(qs);

    int b = blockIdx.z, grp = blockIdx.x;
    int m0 = grp * 128, n0 = blockIdx.y * 128;
    int t = threadIdx.x, lane = t & 31, w = t >> 5;
    int wr = w >> 2, wc = w & 3;
    int lq = lane >> 2, lr = lane & 3;

    float acc[4][4][4];
#pragma unroll
    for (int mt = 0; mt < 4; mt++)
#pragma unroll
        for (int nt = 0; nt < 4; nt++)
#pragma unroll
            for (int r = 0; r < 4; r++) acc[mt][nt][r] = 0.0f;

    int rA = t >> 3, sA = t & 7;
    int rB = t >> 4, sB = t & 15;
    const __nv_bfloat16* gA0 = g_wt + (size_t)(m0 + rA) * 256 + sA * 8;
    const __nv_bfloat16* gB0 = g_xh + ((size_t)b * 256 + rB) * NPOS + n0 + sB * 8;
    uint32_t dA0 = rA * 144 + sA * 16;
    uint32_t dB0 = 18432 + rB * 272 + sB * 16;

#define LOADSTAGE(s, k0)                                                        \
    {                                                                           \
        uint32_t stb = sb + (s) * QST;                                          \
        _Pragma("unroll")                                                       \
        for (int j = 0; j < 4; j++) {                                           \
            cpa16(stb + dA0 + 4608 * j, gA0 + (k0) + 8192 * j);                 \
            cpa16(stb + dB0 + 4352 * j, gB0 + (size_t)((k0) + 16 * j) * NPOS);  \
        }                                                                       \
        CPA_COMMIT();                                                           \
    }

    uint32_t aOff = (uint32_t)(wr * 64 + (lane & 15)) * 144 + ((lane >> 4) << 3) * 2;
    uint32_t bOff = 18432 + (uint32_t)(((lane >> 3) & 1) * 8 + (lane & 7)) * 272 +
                    (uint32_t)(wc * 32 + ((lane >> 4) << 3)) * 2;

    LOADSTAGE(0, 0);
    LOADSTAGE(1, 64);

    for (int kk = 0; kk < 4; kk++) {
        int st = kk % 3;
        if (kk < 3) { CPA_WAIT1(); } else { CPA_WAIT0(); }
        __syncthreads();
        if (kk + 2 < 4) LOADSTAGE((kk + 2) % 3, (kk + 2) * 64);
        uint32_t stb = sb + st * QST;
#pragma unroll
        for (int kh = 0; kh < 4; kh++) {
            uint32_t af[4][4];
#pragma unroll
            for (int mt = 0; mt < 4; mt++)
                ldm_x4(af[mt], stb + aOff + mt * 2304 + kh * 32);
            uint32_t bfr[4][2];
#pragma unroll
            for (int pr = 0; pr < 2; pr++) {
                uint32_t r0, r1, r2, r3;
                ldm_x4t(r0, r1, r2, r3, stb + bOff + kh * 4352 + pr * 32);
                bfr[2 * pr][0] = r0; bfr[2 * pr][1] = r1;
                bfr[2 * pr + 1][0] = r2; bfr[2 * pr + 1][1] = r3;
            }
#pragma unroll
            for (int mt = 0; mt < 4; mt++)
#pragma unroll
                for (int nt = 0; nt < 4; nt++) mma_bf16(acc[mt][nt], af[mt], bfr[nt]);
        }
    }

    const float* fb = g_film + b * 512;
    __nv_bfloat16* C = g_qkvh + (size_t)b * 384 * NPOS;
#pragma unroll
    for (int mt = 0; mt < 4; mt++) {
        int mA = m0 + wr * 64 + mt * 16 + lq;
        int mB = mA + 8;
        float aA, bA, aB, bB;
        filmAB(mA, fb, aA, bA);
        filmAB(mB, fb, aB, bB);
#pragma unroll
        for (int nt = 0; nt < 4; nt++) {
            int cc = n0 + wc * 32 + nt * 8 + 2 * lr;
            __nv_bfloat162 o0 = __floats2bfloat162_rn(fmaf(aA, acc[mt][nt][0], bA),
                                                      fmaf(aA, acc[mt][nt][1], bA));
            __nv_bfloat162 o1 = __floats2bfloat162_rn(fmaf(aB, acc[mt][nt][2], bB),
                                                      fmaf(aB, acc[mt][nt][3], bB));
            *(__nv_bfloat162*)&C[(size_t)mA * NPOS + cc] = o0;
            *(__nv_bfloat162*)&C[(size_t)mB * NPOS + cc] = o1;
        }
    }
}

// ================= ctx via mma: no-max exp, dual accumulator chains (R15) =============
#define KSE 520
__global__ void __launch_bounds__(256) ctx_mma() {
    extern __shared__ __nv_bfloat16 cs[];
    __nv_bfloat16* Ks = cs;
    __nv_bfloat16* Vs = cs + 32 * KSE;

    int b = blockIdx.z, h = blockIdx.y, chunk = blockIdx.x;
    int t = threadIdx.x;

    const __nv_bfloat16* Kg = g_qkvh + ((size_t)b * 384 + 128 + h * 32) * NPOS + chunk * 512;
    const __nv_bfloat16* Vg = Kg + (size_t)128 * NPOS;
    for (int i = t; i < 2048; i += 256) {
        int row = i >> 6, col = i & 63;
        *(uint4*)&Ks[row * KSE + col * 8] = *(const uint4*)(Kg + (size_t)row * NPOS + col * 8);
        *(uint4*)&Vs[row * KSE + col * 8] = *(const uint4*)(Vg + (size_t)row * NPOS + col * 8);
    }
    __syncthreads();

    int c = t >> 3, sub = t & 7;
    __nv_bfloat16* Kr = Ks + c * KSE + sub * 64;
    float z = 0.f;
#pragma unroll
    for (int j4 = 0; j4 < 8; j4++) {
        uint4 kv = *(uint4*)&Kr[j4 * 8];
        __nv_bfloat162* kp = (__nv_bfloat162*)&kv;
        uint4 ev;
        __nv_bfloat162* ep = (__nv_bfloat162*)&ev;
#pragma unroll
        for (int p = 0; p < 4; p++) {
            float2 f = __bfloat1622float2(kp[p]);
            __nv_bfloat162 e2 = __floats2bfloat162_rn(__expf(f.x), __expf(f.y));
            ep[p] = e2;
            float2 ef = __bfloat1622float2(e2);
            z += ef.x + ef.y;
        }
        *(uint4*)&Kr[j4 * 8] = ev;
    }
#pragma unroll
    for (int o = 1; o < 8; o <<= 1) z += __shfl_xor_sync(0xffffffffu, z, o);
    if (sub == 0) g_Zp[((size_t)chunk * NB + b) * 128 + h * 32 + c] = z;
    __syncthreads();

    int w = t >> 5, lane = t & 31;
    int mrow = (w & 1) * 16, ncol = (w >> 1) * 8;
    uint32_t Eb = smem_u32(Ks), Vb = smem_u32(Vs);
    uint32_t aAddr = Eb + ((mrow + (lane & 15)) * KSE + ((lane >> 4) << 3)) * 2;
    uint32_t bAddr = Vb + ((ncol + (lane & 7)) * KSE + (((lane >> 3) & 3) << 3)) * 2;
    float acc0[4] = {0.f, 0.f, 0.f, 0.f};
    float acc1[4] = {0.f, 0.f, 0.f, 0.f};
#pragma unroll
    for (int ks = 0; ks < 32; ks += 2) {
        uint32_t a0[4], b0[2], a1[4], b1[2];
        ldm_x4(a0, aAddr + ks * 32);
        ldm_x2(b0, bAddr + ks * 32);
        ldm_x4(a1, aAddr + ks * 32 + 32);
        ldm_x2(b1, bAddr + ks * 32 + 32);
        mma_bf16(acc0, a0, b0);
        mma_bf16(acc1, a1, b1);
    }
    int lq = lane >> 2, lr = lane & 3;
    float* Sp = g_Sp + (((size_t)chunk * NB + b) * 4 + h) * 1024;
    Sp[(mrow + lq) * 32 + ncol + 2 * lr] = acc0[0] + acc1[0];
    Sp[(mrow + lq) * 32 + ncol + 2 * lr + 1] = acc0[1] + acc1[1];
    Sp[(mrow + lq + 8) * 32 + ncol + 2 * lr] = acc0[2] + acc1[2];
    Sp[(mrow + lq + 8) * 32 + ncol + 2 * lr + 1] = acc0[3] + acc1[3];
}

// ---------------- ctxnorm (R15, unchanged) ----------------
__global__ void ctxnorm_kernel() {
    int seg = blockIdx.x, b = blockIdx.y, t = threadIdx.x;
    __shared__ float zs[16];
    if (t < 16) {
        int chan = seg * 16 + t;
        float zz = 0.f;
#pragma unroll
        for (int ch = 0; ch < NCHUNK; ch++) zz += g_Zp[((size_t)ch * NB + b) * 128 + chan];
        zs[t] = zz;
    }
    __syncthreads();
#pragma unroll
    for (int rep = 0; rep < 2; rep++) {
        int i = seg * 512 + rep * 256 + t;
        float s = 0.f;
#pragma unroll
        for (int ch = 0; ch < NCHUNK; ch++) s += g_Sp[((size_t)ch * NB + b) * 4096 + i];
        g_ctx[b * 4096 + i] = s / zs[(i >> 5) - seg * 16];
    }
}

// ---------------- buildM2 (R15, unchanged) ----------------
__global__ void buildM2_kernel(const float* __restrict__ Wout) {
    int rowseg = blockIdx.x, b = blockIdx.y, t = threadIdx.x;
    __shared__ float ctxs[4096];
    const float4* Cg = (const float4*)(g_ctx + b * 4096);
#pragma unroll
    for (int j = 0; j < 4; j++) {
        int i = t + 256 * j;
        *(float4*)&ctxs[i * 4] = Cg[i];
    }
    __syncthreads();
    int row = rowseg * 16 + (t >> 4);
    int sub = t & 15;
    int c0 = sub * 8;
    int g = c0 >> 5;
    const float* wr = Wout + row * 128 + g * 32;
    float wv[32];
#pragma unroll
    for (int e = 0; e < 32; e++) wv[e] = wr[e];
    __nv_bfloat16* Mr = g_Mb + (size_t)b * 32768 + row * 128;
#pragma unroll
    for (int j = 0; j < 8; j++) {
        int c = c0 + j;
        int c2 = c & 31;
        float s = 0.f;
#pragma unroll
        for (int e = 0; e < 32; e++) s += wv[e] * ctxs[g * 1024 + c2 * 32 + e];
        Mr[c] = __float2bfloat16(s);
    }
}

// ---------------- final v4: 256 thr / 64 cols, KW2=68 -> 2 CTAs/SM ----------------
#define KW2 68
#define FO_M   0               // 256*68 = 17408 words
#define FO_Q   17408           // 64*68 = 4352 words
#define FO_B   21760           // 256
#define FO_G   22016           // 256
#define FO_WS  22272           // 8*32 = 256
#define FO_WQ  22528           // 256
#define FO_CS  22784           // 64
#define FO_CQ  22848           // 64
#define F_TOT  22912           // words = 91648 bytes

__global__ void __launch_bounds__(256, 2) final_mma(const float* __restrict__ bout,
                                                    const float* __restrict__ gam,
                                                    float* __restrict__ out) {
    extern __shared__ uint32_t fsm[];
    uint32_t* Msm = fsm + FO_M;
    uint32_t* Qsm = fsm + FO_Q;
    float* bsm = (float*)(fsm + FO_B);
    float* gsm = (float*)(fsm + FO_G);
    float* wsum = (float*)(fsm + FO_WS);
    float* wsq = (float*)(fsm + FO_WQ);
    float* csum = (float*)(fsm + FO_CS);
    float* csq = (float*)(fsm + FO_CQ);

    int b = blockIdx.y, n0 = blockIdx.x * 64, t = threadIdx.x;
    int lane = t & 31, w = t >> 5;
    int wm = w >> 1, wn = w & 1;
    int lq = lane >> 2, lr = lane & 3;

    // M tile via one cp.async group (overlaps with register q softmax below)
    const __nv_bfloat16* Mg = g_Mb + (size_t)b * 32768;
#pragma unroll
    for (int j = 0; j < 16; j++) {
        int c = t + 256 * j;           // 4096 chunks of 16B
        int row = c >> 4, seg = c & 15;
        cpa16(smem_u32(&Msm[row * KW2 + seg * 4]), Mg + row * 128 + seg * 8);
    }
    CPA_COMMIT();

    bsm[t] = bout[t];
    gsm[t] = gam[t];

    // q softmax from global into Qsm fragments: thread = (head h, col)
    {
        int h = t >> 6, col = t & 63;
        const __nv_bfloat16* Qc = g_qkvh + (size_t)b * 384 * NPOS + (size_t)(h * 32) * NPOS + n0 + col;
        float v[32];
        float ssum = 0.f;
#pragma unroll
        for (int i = 0; i < 32; i++) {
            v[i] = __expf(__bfloat162float(Qc[(size_t)i * NPOS]));
            ssum += v[i];
        }
        float inv = SCALE / ssum;
#pragma unroll
        for (int i2 = 0; i2 < 16; i2++) {
            __nv_bfloat162 p = __floats2bfloat162_rn(v[2 * i2] * inv, v[2 * i2 + 1] * inv);
            Qsm[col * KW2 + h * 16 + i2] = *(uint32_t*)&p;
        }
    }
    CPA_WAIT0();
    __syncthreads();

    float acc[4][4][4];
#pragma unroll
    for (int mt = 0; mt < 4; mt++)
#pragma unroll
        for (int nt = 0; nt < 4; nt++)
#pragma unroll
            for (int r = 0; r < 4; r++) acc[mt][nt][r] = 0.0f;

#pragma unroll
    for (int ks = 0; ks < 8; ks++) {
        int ksw = ks * 8;
        uint32_t af[4][4], bfr[4][2];
#pragma unroll
        for (int mt = 0; mt < 4; mt++) {
            int r0 = wm * 64 + mt * 16 + lq;
            af[mt][0] = Msm[r0 * KW2 + ksw + lr];
            af[mt][1] = Msm[(r0 + 8) * KW2 + ksw + lr];
            af[mt][2] = Msm[r0 * KW2 + ksw + lr + 4];
            af[mt][3] = Msm[(r0 + 8) * KW2 + ksw + lr + 4];
        }
#pragma unroll
        for (int nt = 0; nt < 4; nt++) {
            int n = wn * 32 + nt * 8 + lq;
            bfr[nt][0] = Qsm[n * KW2 + ksw + lr];
            bfr[nt][1] = Qsm[n * KW2 + ksw + lr + 4];
        }
#pragma unroll
        for (int mt = 0; mt < 4; mt++)
#pragma unroll
            for (int nt = 0; nt < 4; nt++) mma_bf16(acc[mt][nt], af[mt], bfr[nt]);
    }

    // + bias, per-column partial stats
    float ps[4][2], pq[4][2];
#pragma unroll
    for (int nt = 0; nt < 4; nt++)
#pragma unroll
        for (int j = 0; j < 2; j++) { ps[nt][j] = 0.f; pq[nt][j] = 0.f; }
#pragma unroll
    for (int mt = 0; mt < 4; mt++) {
        float b0v = bsm[wm * 64 + mt * 16 + lq];
        float b1v = bsm[wm * 64 + mt * 16 + lq + 8];
#pragma unroll
        for (int nt = 0; nt < 4; nt++) {
            acc[mt][nt][0] += b0v; acc[mt][nt][1] += b0v;
            acc[mt][nt][2] += b1v; acc[mt][nt][3] += b1v;
#pragma unroll
            for (int j = 0; j < 2; j++) {
                float v0 = acc[mt][nt][j], v1 = acc[mt][nt][2 + j];
                ps[nt][j] += v0 + v1;
                pq[nt][j] += v0 * v0 + v1 * v1;
            }
        }
    }
#pragma unroll
    for (int nt = 0; nt < 4; nt++)
#pragma unroll
        for (int j = 0; j < 2; j++) {
#pragma unroll
            for (int o = 4; o <= 16; o <<= 1) {
                ps[nt][j] += __shfl_xor_sync(0xffffffffu, ps[nt][j], o);
                pq[nt][j] += __shfl_xor_sync(0xffffffffu, pq[nt][j], o);
            }
        }
    if (lq == 0) {
#pragma unroll
        for (int nt = 0; nt < 4; nt++)
#pragma unroll
            for (int j = 0; j < 2; j++) {
                wsum[w * 32 + nt * 8 + 2 * lr + j] = ps[nt][j];
                wsq[w * 32 + nt * 8 + 2 * lr + j] = pq[nt][j];
            }
    }
    __syncthreads();
    if (t < 64) {
        int wnc = t >> 5, cl = t & 31;
        float sx = 0.f, sq2 = 0.f;
#pragma unroll
        for (int k = 0; k < 4; k++) {
            sx += wsum[(k * 2 + wnc) * 32 + cl];
            sq2 += wsq[(k * 2 + wnc) * 32 + cl];
        }
        csum[t] = sx;
        csq[t] = sq2;
    }
    __syncthreads();

    float mean[4][2], rs[4][2];
#pragma unroll
    for (int nt = 0; nt < 4; nt++)
#pragma unroll
        for (int j = 0; j < 2; j++) {
            int cg = wn * 32 + nt * 8 + 2 * lr + j;
            float mu = csum[cg] * (1.0f / 256.0f);
            float var = csq[cg] * (1.0f / 256.0f) - mu * mu;
            mean[nt][j] = mu;
            rs[nt][j] = rsqrtf(var + 1e-5f);
        }
#pragma unroll
    for (int mt = 0; mt < 4; mt++) {
        int r0 = wm * 64 + mt * 16 + lq;
        float g0 = gsm[r0], g1 = gsm[r0 + 8];
#pragma unroll
        for (int nt = 0; nt < 4; nt++) {
            int cc = n0 + wn * 32 + nt * 8 + 2 * lr;
            float2 o0, o1;
            o0.x = (acc[mt][nt][0] - mean[nt][0]) * rs[nt][0] * g0;
            o0.y = (acc[mt][nt][1] - mean[nt][1]) * rs[nt][1] * g0;
            o1.x = (acc[mt][nt][2] - mean[nt][0]) * rs[nt][0] * g1;
            o1.y = (acc[mt][nt][3] - mean[nt][1]) * rs[nt][1] * g1;
            *(float2*)&out[((size_t)(b * 256 + r0)) * NPOS + cc] = o0;
            *(float2*)&out[((size_t)(b * 256 + r0 + 8)) * NPOS + cc] = o1;
        }
    }
}

// ---------------- launch ----------------
extern "C" void kernel_launch(void* const* d_in, const int* in_sizes, int n_in,
                              void* d_out, int out_size) {
    (void)in_sizes; (void)n_in; (void)out_size;
    const float* x = (const float*)d_in[0];
    const float* cond = (const float*)d_in[1];
    const float* W_qkv = (const float*)d_in[2];
    const float* W_cond = (const float*)d_in[3];
    const float* b_cond = (const float*)d_in[4];
    const float* W_out = (const float*)d_in[5];
    const float* b_out = (const float*)d_in[6];
    const float* g = (const float*)d_in[7];
    float* out = (float*)d_out;

    film_kernel<<<NB, 512>>>(cond, W_cond, b_cond);
    wconv_kernel<<<96, 1024>>>(W_qkv);
    xconv_kernel<<<(NB * 256 * NPOS) / 1024, 256>>>(x);

    cudaFuncSetAttribute(qkv_mma, cudaFuncAttributeMaxDynamicSharedMemorySize, QKV_SMEM);
    qkv_mma<<<dim3(3, 32, NB), 256, QKV_SMEM>>>();

    int ctx_smem = 2 * 32 * KSE * (int)sizeof(__nv_bfloat16);
    cudaFuncSetAttribute(ctx_mma, cudaFuncAttributeMaxDynamicSharedMemorySize, ctx_smem);
    ctx_mma<<<dim3(NCHUNK, 4, NB), 256, ctx_smem>>>();

    ctxnorm_kernel<<<dim3(8, NB), 256>>>();
    buildM2_kernel<<<dim3(16, NB), 256>>>(W_out);

    int smbytes = F_TOT * (int)sizeof(uint32_t);
    cudaFuncSetAttribute(final_mma, cudaFuncAttributeMaxDynamicSharedMemorySize, smbytes);
    final_mma<<<dim3(64, NB), 256, smbytes>>>(b_out, g, out);
}